// round 2
// baseline (speedup 1.0000x reference)
#include <cuda_runtime.h>
#include <math.h>

// Problem constants (fixed by the dataset)
#define S_LEN 2048
#define NHEAD 16
#define HDIM  256
#define BATCH 2
#define DMODEL 4096
#define NTOK  4096              // BATCH * S_LEN
#define BH    32                // BATCH * NHEAD

#define BK 16

// ---------------- scratch (device globals; no allocations allowed) ----------
__device__ float g_Q [(size_t)NTOK * DMODEL];
__device__ float g_K [(size_t)NTOK * DMODEL];
__device__ float g_V [(size_t)NTOK * DMODEL];
__device__ float g_KC[(size_t)NTOK * DMODEL];
__device__ float g_VC[(size_t)NTOK * DMODEL];
__device__ float g_Kg[(size_t)NTOK * DMODEL];   // [B,H,S,HD]
__device__ float g_Vg[(size_t)NTOK * DMODEL];   // [B,H,S,HD]
__device__ float g_O [(size_t)NTOK * DMODEL];   // [B,S,H,HD]
__device__ float g_Sc[(size_t)BH * S_LEN * S_LEN]; // scores/probs
__device__ int   g_idx[5][NTOK];                // normalized int32 index arrays

// ---------------- index dtype normalization ---------------------------------
// The reference declares the index tensors as int64, but JAX with default
// (x64-disabled) config materializes them as int32. Values are < 4096, so for
// a true int64 array the odd 32-bit words (high halves) are all zero; for an
// arange-style int32 array word[1] == 1 != 0. Sniff and normalize to int32.
__global__ __launch_bounds__(256)
void conv_idx_kernel(const unsigned int* __restrict__ raw,
                     int* __restrict__ out, int n) {
    bool is64 = (raw[1] == 0u) && (raw[3] == 0u) && (raw[5] == 0u);
    int i = blockIdx.x * 256 + threadIdx.x;
    if (i < n) out[i] = is64 ? (int)raw[2 * i] : (int)raw[i];
}

// ---------------- packed fp32x2 helpers -------------------------------------
__device__ __forceinline__ unsigned long long pack2(float x, float y) {
    unsigned long long r;
    asm("mov.b64 %0, {%1, %2};" : "=l"(r)
        : "r"(__float_as_uint(x)), "r"(__float_as_uint(y)));
    return r;
}
__device__ __forceinline__ void unpack2(unsigned long long v, float& x, float& y) {
    unsigned int lo, hi;
    asm("mov.b64 {%0, %1}, %2;" : "=r"(lo), "=r"(hi) : "l"(v));
    x = __uint_as_float(lo); y = __uint_as_float(hi);
}
__device__ __forceinline__ void ffma2(unsigned long long& d,
                                      unsigned long long a,
                                      unsigned long long b) {
    asm("fma.rn.f32x2 %0, %1, %2, %0;" : "+l"(d) : "l"(a), "l"(b));
}

// 8x8 microkernel over a BK x 128 x 128 shared tile pair.
// As, Bs: [BK][128] row-major. acc[i][j] holds C(tm+i, tn+2j), C(tm+i, tn+2j+1).
__device__ __forceinline__ void mm8x8(const float* __restrict__ As,
                                      const float* __restrict__ Bs,
                                      int tm, int tn,
                                      unsigned long long acc[8][4]) {
#pragma unroll
    for (int kk = 0; kk < BK; kk++) {
        const float* ar = As + kk * 128 + tm;
        const float* br = Bs + kk * 128 + tn;
        float4 a0 = *(const float4*)ar;
        float4 a1 = *(const float4*)(ar + 4);
        float4 b0 = *(const float4*)br;
        float4 b1 = *(const float4*)(br + 4);
        unsigned long long bp0 = pack2(b0.x, b0.y);
        unsigned long long bp1 = pack2(b0.z, b0.w);
        unsigned long long bp2 = pack2(b1.x, b1.y);
        unsigned long long bp3 = pack2(b1.z, b1.w);
        float av[8] = {a0.x, a0.y, a0.z, a0.w, a1.x, a1.y, a1.z, a1.w};
#pragma unroll
        for (int i = 0; i < 8; i++) {
            unsigned long long ap = pack2(av[i], av[i]);
            ffma2(acc[i][0], ap, bp0);
            ffma2(acc[i][1], ap, bp1);
            ffma2(acc[i][2], ap, bp2);
            ffma2(acc[i][3], ap, bp3);
        }
    }
}

// ---------------- 4096x4096x4096 NT GEMM:  C = A * W^T ----------------------
__global__ __launch_bounds__(256, 2)
void sgemm_nt_4k(const float* __restrict__ A, const float* __restrict__ W,
                 float* __restrict__ C) {
    __shared__ __align__(16) float As[BK * 128];
    __shared__ __align__(16) float Bs[BK * 128];
    const int tid = threadIdx.x;
    const int m0 = blockIdx.y * 128, n0 = blockIdx.x * 128;
    const int lr = tid >> 2;
    const int lc = (tid & 3) * 4;
    const int tm = (tid >> 4) * 8, tn = (tid & 15) * 8;
    unsigned long long acc[8][4];
#pragma unroll
    for (int i = 0; i < 8; i++)
#pragma unroll
        for (int j = 0; j < 4; j++) acc[i][j] = 0ULL;

    for (int k0 = 0; k0 < DMODEL; k0 += BK) {
#pragma unroll
        for (int i = 0; i < 2; i++) {
            int r = lr + i * 64;
            float4 a = *(const float4*)&A[(size_t)(m0 + r) * DMODEL + k0 + lc];
            As[(lc + 0) * 128 + r] = a.x; As[(lc + 1) * 128 + r] = a.y;
            As[(lc + 2) * 128 + r] = a.z; As[(lc + 3) * 128 + r] = a.w;
            float4 b = *(const float4*)&W[(size_t)(n0 + r) * DMODEL + k0 + lc];
            Bs[(lc + 0) * 128 + r] = b.x; Bs[(lc + 1) * 128 + r] = b.y;
            Bs[(lc + 2) * 128 + r] = b.z; Bs[(lc + 3) * 128 + r] = b.w;
        }
        __syncthreads();
        mm8x8(As, Bs, tm, tn, acc);
        __syncthreads();
    }
#pragma unroll
    for (int i = 0; i < 8; i++) {
        float c[8];
        unpack2(acc[i][0], c[0], c[1]); unpack2(acc[i][1], c[2], c[3]);
        unpack2(acc[i][2], c[4], c[5]); unpack2(acc[i][3], c[6], c[7]);
        float4* p = (float4*)&C[(size_t)(m0 + tm + i) * DMODEL + n0 + tn];
        p[0] = make_float4(c[0], c[1], c[2], c[3]);
        p[1] = make_float4(c[4], c[5], c[6], c[7]);
    }
}

// ---------------- RoPE (first 64 dims of each head, in place on Q and K) ----
__global__ __launch_bounds__(256)
void rope_kernel(float* __restrict__ Q, float* __restrict__ K,
                 const int* __restrict__ pos_ids) {
    int gid = blockIdx.x * 256 + threadIdx.x;      // over NTOK*NHEAD*32
    int f   = gid & 31;
    int h   = (gid >> 5) & 15;
    int tok = gid >> 9;
    int pos = pos_ids[tok];
    float inv = powf(10000.0f, -(2.0f * (float)f) / 64.0f);
    float ang = (float)pos * inv;
    float c = cosf(ang), s = sinf(ang);
    size_t base = (size_t)tok * DMODEL + h * HDIM + 2 * f;
    float q0 = Q[base], q1 = Q[base + 1];
    Q[base]     = c * q0 - s * q1;
    Q[base + 1] = s * q0 + c * q1;
    float k0 = K[base], k1 = K[base + 1];
    K[base]     = c * k0 - s * k1;
    K[base + 1] = s * k0 + c * k1;
}

// ---------------- cache copy / scatter / gather ------------------------------
__global__ __launch_bounds__(256)
void copy_cache(float4* __restrict__ KC, float4* __restrict__ VC,
                const float4* __restrict__ lpk, const float4* __restrict__ lpv) {
    int i = blockIdx.x * 256 + threadIdx.x;        // over NTOK*1024
    KC[i] = lpk[i];
    VC[i] = lpv[i];
}

__global__ __launch_bounds__(256)
void scatter_kernel(float4* __restrict__ KC, float4* __restrict__ VC,
                    const float4* __restrict__ K, const float4* __restrict__ V,
                    const int* __restrict__ nkl,
                    const int* __restrict__ nvl) {
    int i = blockIdx.x * 256 + threadIdx.x;        // over NTOK*1024
    int off = i & 1023;
    int tok = i >> 10;
    int dk = nkl[tok];
    int dv = nvl[tok];
    KC[(size_t)dk * 1024 + off] = K[i];
    VC[(size_t)dv * 1024 + off] = V[i];
}

__global__ __launch_bounds__(256)
void gather_kernel(float4* __restrict__ Kg, float4* __restrict__ Vg,
                   const float4* __restrict__ KC, const float4* __restrict__ VC,
                   const int* __restrict__ vki,
                   const int* __restrict__ vvi) {
    int i = blockIdx.x * 256 + threadIdx.x;        // over NTOK*1024 (float4)
    int d4 = i & 63;
    int t  = (i >> 6) & 2047;
    int h  = (i >> 17) & 15;
    int b  = i >> 21;
    int sk = vki[b * S_LEN + t];
    int sv = vvi[b * S_LEN + t];
    Kg[i] = KC[(size_t)sk * 1024 + h * 64 + d4];
    Vg[i] = VC[(size_t)sv * 1024 + h * 64 + d4];
}

// ---------------- QK^T with causal mask + scale + attention_mask ------------
// Sc[bh][m][n] = (n<=m) ? dot(Q_m, K_n)/16 + am[b][n] : -1e30
__global__ __launch_bounds__(256, 2)
void qk_gemm(const float* __restrict__ Qb, const float* __restrict__ Kg,
             const float* __restrict__ am, float* __restrict__ Sc) {
    const int tid = threadIdx.x;
    const int bh = blockIdx.z;
    const int b = bh >> 4, h = bh & 15;
    const int m0 = blockIdx.y * 128, n0 = blockIdx.x * 128;
    float* Cb = Sc + (size_t)bh * S_LEN * S_LEN;

    if (n0 > m0 + 127) {  // fully masked tile: constant fill, no compute
        float4 neg = make_float4(-1e30f, -1e30f, -1e30f, -1e30f);
        for (int i = tid; i < 128 * 32; i += 256) {
            int r = i >> 5;
            int c4 = (i & 31) << 2;
            *(float4*)&Cb[(size_t)(m0 + r) * S_LEN + n0 + c4] = neg;
        }
        return;
    }

    __shared__ __align__(16) float As[BK * 128];
    __shared__ __align__(16) float Bs[BK * 128];
    const float* Arow = Qb + (size_t)b * S_LEN * DMODEL + h * HDIM; // lda=DMODEL
    const float* Brow = Kg + (size_t)bh * S_LEN * HDIM;             // ldb=HDIM
    const int lr = tid >> 2;
    const int lc = (tid & 3) * 4;
    const int tm = (tid >> 4) * 8, tn = (tid & 15) * 8;
    unsigned long long acc[8][4];
#pragma unroll
    for (int i = 0; i < 8; i++)
#pragma unroll
        for (int j = 0; j < 4; j++) acc[i][j] = 0ULL;

    for (int k0 = 0; k0 < HDIM; k0 += BK) {
#pragma unroll
        for (int i = 0; i < 2; i++) {
            int r = lr + i * 64;
            float4 a = *(const float4*)&Arow[(size_t)(m0 + r) * DMODEL + k0 + lc];
            As[(lc + 0) * 128 + r] = a.x; As[(lc + 1) * 128 + r] = a.y;
            As[(lc + 2) * 128 + r] = a.z; As[(lc + 3) * 128 + r] = a.w;
            float4 bb = *(const float4*)&Brow[(size_t)(n0 + r) * HDIM + k0 + lc];
            Bs[(lc + 0) * 128 + r] = bb.x; Bs[(lc + 1) * 128 + r] = bb.y;
            Bs[(lc + 2) * 128 + r] = bb.z; Bs[(lc + 3) * 128 + r] = bb.w;
        }
        __syncthreads();
        mm8x8(As, Bs, tm, tn, acc);
        __syncthreads();
    }

    const float scale = 1.0f / 16.0f;
#pragma unroll
    for (int i = 0; i < 8; i++) {
        float c[8];
        unpack2(acc[i][0], c[0], c[1]); unpack2(acc[i][1], c[2], c[3]);
        unpack2(acc[i][2], c[4], c[5]); unpack2(acc[i][3], c[6], c[7]);
        int m = m0 + tm + i;
        float v[8];
#pragma unroll
        for (int j = 0; j < 8; j++) {
            int n = n0 + tn + j;
            v[j] = (n <= m) ? (c[j] * scale + am[b * S_LEN + n]) : -1e30f;
        }
        float4* p = (float4*)&Cb[(size_t)m * S_LEN + n0 + tn];
        p[0] = make_float4(v[0], v[1], v[2], v[3]);
        p[1] = make_float4(v[4], v[5], v[6], v[7]);
    }
}

// ---------------- row softmax over 2048 keys --------------------------------
__global__ __launch_bounds__(256)
void softmax_kernel(float* __restrict__ Sc) {
    __shared__ float sh[8];
    const size_t base = (size_t)blockIdx.x * S_LEN;
    const int tid = threadIdx.x;
    const int lane = tid & 31, wid = tid >> 5;
    float v[8];
    float m = -INFINITY;
#pragma unroll
    for (int i = 0; i < 8; i++) {
        v[i] = Sc[base + tid + i * 256];
        m = fmaxf(m, v[i]);
    }
#pragma unroll
    for (int o = 16; o; o >>= 1) m = fmaxf(m, __shfl_xor_sync(0xffffffffu, m, o));
    if (lane == 0) sh[wid] = m;
    __syncthreads();
    float mall = sh[0];
#pragma unroll
    for (int w = 1; w < 8; w++) mall = fmaxf(mall, sh[w]);
    __syncthreads();
    float s = 0.f;
#pragma unroll
    for (int i = 0; i < 8; i++) {
        v[i] = __expf(v[i] - mall);
        s += v[i];
    }
#pragma unroll
    for (int o = 16; o; o >>= 1) s += __shfl_xor_sync(0xffffffffu, s, o);
    if (lane == 0) sh[wid] = s;
    __syncthreads();
    float sall = 0.f;
#pragma unroll
    for (int w = 0; w < 8; w++) sall += sh[w];
    float inv = 1.0f / sall;
#pragma unroll
    for (int i = 0; i < 8; i++) Sc[base + tid + i * 256] = v[i] * inv;
}

// ---------------- PV GEMM (NN): O[b,s,h,:] = P * V --------------------------
__global__ __launch_bounds__(256, 2)
void pv_gemm(const float* __restrict__ Sc, const float* __restrict__ Vg,
             float* __restrict__ O) {
    __shared__ __align__(16) float As[BK * 128];
    __shared__ __align__(16) float Bs[BK * 128];
    const int tid = threadIdx.x;
    const int bh = blockIdx.z;
    const int b = bh >> 4, h = bh & 15;
    const int m0 = blockIdx.y * 128, n0 = blockIdx.x * 128;
    const float* A  = Sc + (size_t)bh * S_LEN * S_LEN;   // [m][k], lda=S_LEN
    const float* Bv = Vg + (size_t)bh * S_LEN * HDIM;    // [k][n], ldb=HDIM
    const int lr = tid >> 2;
    const int lc = (tid & 3) * 4;
    const int r2 = tid >> 4;           // 0..15 for Bs direct load
    const int c0 = (tid & 15) * 8;
    const int tm = (tid >> 4) * 8, tn = (tid & 15) * 8;
    unsigned long long acc[8][4];
#pragma unroll
    for (int i = 0; i < 8; i++)
#pragma unroll
        for (int j = 0; j < 4; j++) acc[i][j] = 0ULL;

    const int kmax = m0 + 128;  // causal: P[m][k]==0 for k>m
    for (int k0 = 0; k0 < kmax; k0 += BK) {
#pragma unroll
        for (int i = 0; i < 2; i++) {
            int r = lr + i * 64;
            float4 a = *(const float4*)&A[(size_t)(m0 + r) * S_LEN + k0 + lc];
            As[(lc + 0) * 128 + r] = a.x; As[(lc + 1) * 128 + r] = a.y;
            As[(lc + 2) * 128 + r] = a.z; As[(lc + 3) * 128 + r] = a.w;
        }
        float4 b0 = *(const float4*)&Bv[(size_t)(k0 + r2) * HDIM + n0 + c0];
        float4 b1 = *(const float4*)&Bv[(size_t)(k0 + r2) * HDIM + n0 + c0 + 4];
        *(float4*)&Bs[r2 * 128 + c0]     = b0;
        *(float4*)&Bs[r2 * 128 + c0 + 4] = b1;
        __syncthreads();
        mm8x8(As, Bs, tm, tn, acc);
        __syncthreads();
    }
#pragma unroll
    for (int i = 0; i < 8; i++) {
        float c[8];
        unpack2(acc[i][0], c[0], c[1]); unpack2(acc[i][1], c[2], c[3]);
        unpack2(acc[i][2], c[4], c[5]); unpack2(acc[i][3], c[6], c[7]);
        size_t tok = (size_t)b * S_LEN + (m0 + tm + i);
        float4* p = (float4*)&O[tok * DMODEL + h * HDIM + n0 + tn];
        p[0] = make_float4(c[0], c[1], c[2], c[3]);
        p[1] = make_float4(c[4], c[5], c[6], c[7]);
    }
}

// ---------------- host launcher ---------------------------------------------
extern "C" void kernel_launch(void* const* d_in, const int* in_sizes, int n_in,
                              void* d_out, int out_size) {
    (void)in_sizes; (void)n_in; (void)out_size;
    const float* hs  = (const float*)d_in[0];
    const float* Wq  = (const float*)d_in[1];
    const float* Wk  = (const float*)d_in[2];
    const float* Wv  = (const float*)d_in[3];
    const float* Wo  = (const float*)d_in[4];
    const float* lpk = (const float*)d_in[5];
    const float* lpv = (const float*)d_in[6];
    const float* am  = (const float*)d_in[7];
    const unsigned int* pos_raw = (const unsigned int*)d_in[8];
    const unsigned int* nkl_raw = (const unsigned int*)d_in[9];
    const unsigned int* nvl_raw = (const unsigned int*)d_in[10];
    const unsigned int* vki_raw = (const unsigned int*)d_in[11];
    const unsigned int* vvi_raw = (const unsigned int*)d_in[12];
    float* out = (float*)d_out;

    float *Q, *K, *V, *KC, *VC, *Kg, *Vg, *O, *Sc;
    int* idx;
    cudaGetSymbolAddress((void**)&Q,  g_Q);
    cudaGetSymbolAddress((void**)&K,  g_K);
    cudaGetSymbolAddress((void**)&V,  g_V);
    cudaGetSymbolAddress((void**)&KC, g_KC);
    cudaGetSymbolAddress((void**)&VC, g_VC);
    cudaGetSymbolAddress((void**)&Kg, g_Kg);
    cudaGetSymbolAddress((void**)&Vg, g_Vg);
    cudaGetSymbolAddress((void**)&O,  g_O);
    cudaGetSymbolAddress((void**)&Sc, g_Sc);
    cudaGetSymbolAddress((void**)&idx, g_idx);
    int* pos = idx + 0 * NTOK;
    int* nkl = idx + 1 * NTOK;
    int* nvl = idx + 2 * NTOK;
    int* vki = idx + 3 * NTOK;
    int* vvi = idx + 4 * NTOK;

    // normalize index dtypes (int64-declared arrays may arrive as int32)
    conv_idx_kernel<<<16, 256>>>(pos_raw, pos, NTOK);
    conv_idx_kernel<<<16, 256>>>(nkl_raw, nkl, NTOK);
    conv_idx_kernel<<<16, 256>>>(nvl_raw, nvl, NTOK);
    conv_idx_kernel<<<16, 256>>>(vki_raw, vki, NTOK);
    conv_idx_kernel<<<16, 256>>>(vvi_raw, vvi, NTOK);

    dim3 gproj(32, 32);
    sgemm_nt_4k<<<gproj, 256>>>(hs, Wq, Q);
    sgemm_nt_4k<<<gproj, 256>>>(hs, Wk, K);
    sgemm_nt_4k<<<gproj, 256>>>(hs, Wv, V);

    rope_kernel<<<8192, 256>>>(Q, K, pos);

    copy_cache<<<16384, 256>>>((float4*)KC, (float4*)VC,
                               (const float4*)lpk, (const float4*)lpv);
    scatter_kernel<<<16384, 256>>>((float4*)KC, (float4*)VC,
                                   (const float4*)K, (const float4*)V, nkl, nvl);
    gather_kernel<<<16384, 256>>>((float4*)Kg, (float4*)Vg,
                                  (const float4*)KC, (const float4*)VC, vki, vvi);

    qk_gemm<<<dim3(16, 16, 32), 256>>>(Q, Kg, am, Sc);
    softmax_kernel<<<65536, 256>>>(Sc);
    pv_gemm<<<dim3(2, 16, 32), 256>>>(Sc, Vg, O);

    sgemm_nt_4k<<<gproj, 256>>>(O, Wo, out);
}

// round 4
// speedup vs baseline: 2.0457x; 2.0457x over previous
#include <cuda_runtime.h>
#include <cuda_bf16.h>
#include <math.h>
#include <stdint.h>

// Problem constants (fixed by the dataset)
#define S_LEN 2048
#define NHEAD 16
#define HDIM  256
#define BATCH 2
#define DMODEL 4096
#define NTOK  4096              // BATCH * S_LEN
#define BH    32                // BATCH * NHEAD

#define BK 16

// ---------------- scratch (device globals; no allocations allowed) ----------
__device__ float g_Q [(size_t)NTOK * DMODEL];
__device__ float g_K [(size_t)NTOK * DMODEL];
__device__ float g_V [(size_t)NTOK * DMODEL];
__device__ float g_KC[(size_t)NTOK * DMODEL];
__device__ float g_VC[(size_t)NTOK * DMODEL];
__device__ float g_Kg[(size_t)NTOK * DMODEL];   // [B,H,S,HD]
__device__ float g_Vg[(size_t)NTOK * DMODEL];   // [B,H,S,HD]
__device__ float g_O [(size_t)NTOK * DMODEL];   // [B,S,H,HD]
__device__ float g_Sc[(size_t)BH * S_LEN * S_LEN]; // scores/probs
__device__ int   g_idx[5][NTOK];                // normalized int32 index arrays
// bf16 split buffers for tensor-core GEMMs
__device__ __nv_bfloat16 g_Xh[(size_t)NTOK * DMODEL];
__device__ __nv_bfloat16 g_Xl[(size_t)NTOK * DMODEL];
__device__ __nv_bfloat16 g_Wh[(size_t)DMODEL * DMODEL];
__device__ __nv_bfloat16 g_Wl[(size_t)DMODEL * DMODEL];

// ============================================================================
// helpers
// ============================================================================
__device__ __forceinline__ uint32_t smem_u32(const void* p) {
    uint32_t a;
    asm("{ .reg .u64 t; cvta.to.shared.u64 t, %1; cvt.u32.u64 %0, t; }"
        : "=r"(a) : "l"(p));
    return a;
}
__device__ __forceinline__ void cp_async16(uint32_t dst, const void* src) {
    asm volatile("cp.async.cg.shared.global [%0], [%1], 16;"
                 :: "r"(dst), "l"(src) : "memory");
}
__device__ __forceinline__ void cp_commit() {
    asm volatile("cp.async.commit_group;" ::: "memory");
}
__device__ __forceinline__ void cp_wait1() {
    asm volatile("cp.async.wait_group 1;" ::: "memory");
}
__device__ __forceinline__ void mma_bf16(float* d, const uint32_t* a, const uint32_t* b) {
    asm volatile(
        "mma.sync.aligned.m16n8k16.row.col.f32.bf16.bf16.f32 "
        "{%0,%1,%2,%3}, {%4,%5,%6,%7}, {%8,%9}, {%0,%1,%2,%3};"
        : "+f"(d[0]), "+f"(d[1]), "+f"(d[2]), "+f"(d[3])
        : "r"(a[0]), "r"(a[1]), "r"(a[2]), "r"(a[3]), "r"(b[0]), "r"(b[1]));
}

// ============================================================================
// bf16-split GEMM on mma.sync:  C[4096x4096] = A * W^T (both K-major, ld=4096)
// D = Ah*Bh + Ah*Bl + Al*Bh  (fp32 accum).  CTA tile 128x256x32, 8 warps
// (2Mx4N, warp tile 64x64), 3-stage cp.async pipeline, 80B-padded smem rows.
// ============================================================================
#define GBM 128
#define GBN 256
#define GBK 32
#define ROWB 80                         // smem row stride (bytes) = 64 data + 16 pad
#define SM_A_SZ (GBM * ROWB)            // 10240
#define SM_B_SZ (GBN * ROWB)            // 20480
#define OFF_AH 0
#define OFF_AL SM_A_SZ
#define OFF_BH (2 * SM_A_SZ)
#define OFF_BL (2 * SM_A_SZ + SM_B_SZ)
#define STAGE_B (2 * SM_A_SZ + 2 * SM_B_SZ)  // 61440
#define PIPE 3
#define GEMM_SMEM (PIPE * STAGE_B)      // 184320
#define KITERS (DMODEL / GBK)           // 128

__global__ __launch_bounds__(256, 1)
void gemm_split_mma(const __nv_bfloat16* __restrict__ Agh,
                    const __nv_bfloat16* __restrict__ Agl,
                    const __nv_bfloat16* __restrict__ Bgh,
                    const __nv_bfloat16* __restrict__ Bgl,
                    float* __restrict__ C) {
    extern __shared__ __align__(16) char sm[];
    const uint32_t sbase = smem_u32(sm);
    const int tid  = threadIdx.x;
    const int wid  = tid >> 5;
    const int lane = tid & 31;
    const int g = lane >> 2, t = lane & 3;
    const int wm = wid >> 2, wn = wid & 3;       // 2 x 4 warp grid
    const int m0 = blockIdx.y * GBM;
    const int n0 = blockIdx.x * GBN;

    float acc[4][8][4];
#pragma unroll
    for (int i = 0; i < 4; i++)
#pragma unroll
        for (int j = 0; j < 8; j++)
#pragma unroll
            for (int r = 0; r < 4; r++) acc[i][j][r] = 0.f;

    // ---- async load of one 32-k slab into stage s ----
    auto issue = [&](int it, int s) {
        const int k0 = it * GBK;
        const uint32_t stg = sbase + s * STAGE_B;
#pragma unroll
        for (int q = 0; q < 12; q++) {
            int c = tid + q * 256;               // 0..3071
            if (c < 1024) {                      // A tiles (h then l)
                int split = c >> 9;
                int idx = c & 511;
                int row = idx >> 2, kc = idx & 3;
                const __nv_bfloat16* src = (split ? Agl : Agh)
                    + (size_t)(m0 + row) * DMODEL + k0 + kc * 8;
                cp_async16(stg + (split ? OFF_AL : OFF_AH) + row * ROWB + kc * 16, src);
            } else {                             // B tiles (h then l)
                int c2 = c - 1024;
                int split = c2 >> 10;
                int idx = c2 & 1023;
                int row = idx >> 2, kc = idx & 3;
                const __nv_bfloat16* src = (split ? Bgl : Bgh)
                    + (size_t)(n0 + row) * DMODEL + k0 + kc * 8;
                cp_async16(stg + (split ? OFF_BL : OFF_BH) + row * ROWB + kc * 16, src);
            }
        }
    };

    issue(0, 0); cp_commit();
    issue(1, 1); cp_commit();

    for (int it = 0; it < KITERS; it++) {
        cp_wait1();
        __syncthreads();
        const char* stg = sm + (it % PIPE) * STAGE_B;

#pragma unroll
        for (int ks = 0; ks < 2; ks++) {
            const int kb = ks * 32 + t * 4;      // k byte offset within row
            uint32_t ah[4][4], al[4][4], bh[8][2], bl[8][2];
#pragma unroll
            for (int i = 0; i < 4; i++) {
                int r0 = wm * 64 + i * 16 + g;
                const char* p = stg + OFF_AH + r0 * ROWB + kb;
                ah[i][0] = *(const uint32_t*)(p);
                ah[i][1] = *(const uint32_t*)(p + 8 * ROWB);
                ah[i][2] = *(const uint32_t*)(p + 16);
                ah[i][3] = *(const uint32_t*)(p + 8 * ROWB + 16);
            }
#pragma unroll
            for (int j = 0; j < 8; j++) {
                int n = wn * 64 + j * 8 + g;
                const char* p = stg + OFF_BH + n * ROWB + kb;
                bh[j][0] = *(const uint32_t*)(p);
                bh[j][1] = *(const uint32_t*)(p + 16);
            }
#pragma unroll
            for (int i = 0; i < 4; i++)
#pragma unroll
                for (int j = 0; j < 8; j++) mma_bf16(acc[i][j], ah[i], bh[j]);

#pragma unroll
            for (int j = 0; j < 8; j++) {
                int n = wn * 64 + j * 8 + g;
                const char* p = stg + OFF_BL + n * ROWB + kb;
                bl[j][0] = *(const uint32_t*)(p);
                bl[j][1] = *(const uint32_t*)(p + 16);
            }
#pragma unroll
            for (int i = 0; i < 4; i++)
#pragma unroll
                for (int j = 0; j < 8; j++) mma_bf16(acc[i][j], ah[i], bl[j]);

#pragma unroll
            for (int i = 0; i < 4; i++) {
                int r0 = wm * 64 + i * 16 + g;
                const char* p = stg + OFF_AL + r0 * ROWB + kb;
                al[i][0] = *(const uint32_t*)(p);
                al[i][1] = *(const uint32_t*)(p + 8 * ROWB);
                al[i][2] = *(const uint32_t*)(p + 16);
                al[i][3] = *(const uint32_t*)(p + 8 * ROWB + 16);
            }
#pragma unroll
            for (int i = 0; i < 4; i++)
#pragma unroll
                for (int j = 0; j < 8; j++) mma_bf16(acc[i][j], al[i], bh[j]);
        }

        if (it + 2 < KITERS) issue(it + 2, (it + 2) % PIPE);
        cp_commit();                             // empty groups keep counts aligned
    }

    // ---- epilogue ----
#pragma unroll
    for (int i = 0; i < 4; i++) {
        int m = m0 + wm * 64 + i * 16 + g;
#pragma unroll
        for (int j = 0; j < 8; j++) {
            int n = n0 + wn * 64 + j * 8 + t * 2;
            *(float2*)&C[(size_t)m * DMODEL + n]       = make_float2(acc[i][j][0], acc[i][j][1]);
            *(float2*)&C[(size_t)(m + 8) * DMODEL + n] = make_float2(acc[i][j][2], acc[i][j][3]);
        }
    }
}

// ---------------- fp32 -> (bf16 hi, bf16 lo) split conversion ----------------
__global__ __launch_bounds__(256)
void conv_split_kernel(const float4* __restrict__ x,
                       __nv_bfloat162* __restrict__ hi,
                       __nv_bfloat162* __restrict__ lo) {
    int i = blockIdx.x * 256 + threadIdx.x;     // over N/4 float4s
    float4 v = x[i];
    __nv_bfloat16 h0 = __float2bfloat16(v.x);
    __nv_bfloat16 h1 = __float2bfloat16(v.y);
    __nv_bfloat16 h2 = __float2bfloat16(v.z);
    __nv_bfloat16 h3 = __float2bfloat16(v.w);
    __nv_bfloat16 l0 = __float2bfloat16(v.x - __bfloat162float(h0));
    __nv_bfloat16 l1 = __float2bfloat16(v.y - __bfloat162float(h1));
    __nv_bfloat16 l2 = __float2bfloat16(v.z - __bfloat162float(h2));
    __nv_bfloat16 l3 = __float2bfloat16(v.w - __bfloat162float(h3));
    hi[2 * i]     = __halves2bfloat162(h0, h1);
    hi[2 * i + 1] = __halves2bfloat162(h2, h3);
    lo[2 * i]     = __halves2bfloat162(l0, l1);
    lo[2 * i + 1] = __halves2bfloat162(l2, l3);
}

// ---------------- index dtype normalization ---------------------------------
__global__ __launch_bounds__(256)
void conv_idx_kernel(const unsigned int* __restrict__ raw,
                     int* __restrict__ out, int n) {
    bool is64 = (raw[1] == 0u) && (raw[3] == 0u) && (raw[5] == 0u);
    int i = blockIdx.x * 256 + threadIdx.x;
    if (i < n) out[i] = is64 ? (int)raw[2 * i] : (int)raw[i];
}

// ---------------- packed fp32x2 helpers (scalar attention path) -------------
__device__ __forceinline__ unsigned long long pack2(float x, float y) {
    unsigned long long r;
    asm("mov.b64 %0, {%1, %2};" : "=l"(r)
        : "r"(__float_as_uint(x)), "r"(__float_as_uint(y)));
    return r;
}
__device__ __forceinline__ void unpack2(unsigned long long v, float& x, float& y) {
    unsigned int lo, hi;
    asm("mov.b64 {%0, %1}, %2;" : "=r"(lo), "=r"(hi) : "l"(v));
    x = __uint_as_float(lo); y = __uint_as_float(hi);
}
__device__ __forceinline__ void ffma2(unsigned long long& d,
                                      unsigned long long a,
                                      unsigned long long b) {
    asm("fma.rn.f32x2 %0, %1, %2, %0;" : "+l"(d) : "l"(a), "l"(b));
}

__device__ __forceinline__ void mm8x8(const float* __restrict__ As,
                                      const float* __restrict__ Bs,
                                      int tm, int tn,
                                      unsigned long long acc[8][4]) {
#pragma unroll
    for (int kk = 0; kk < BK; kk++) {
        const float* ar = As + kk * 128 + tm;
        const float* br = Bs + kk * 128 + tn;
        float4 a0 = *(const float4*)ar;
        float4 a1 = *(const float4*)(ar + 4);
        float4 b0 = *(const float4*)br;
        float4 b1 = *(const float4*)(br + 4);
        unsigned long long bp0 = pack2(b0.x, b0.y);
        unsigned long long bp1 = pack2(b0.z, b0.w);
        unsigned long long bp2 = pack2(b1.x, b1.y);
        unsigned long long bp3 = pack2(b1.z, b1.w);
        float av[8] = {a0.x, a0.y, a0.z, a0.w, a1.x, a1.y, a1.z, a1.w};
#pragma unroll
        for (int i = 0; i < 8; i++) {
            unsigned long long ap = pack2(av[i], av[i]);
            ffma2(acc[i][0], ap, bp0);
            ffma2(acc[i][1], ap, bp1);
            ffma2(acc[i][2], ap, bp2);
            ffma2(acc[i][3], ap, bp3);
        }
    }
}

// ---------------- RoPE (first 64 dims of each head, in place on Q and K) ----
__global__ __launch_bounds__(256)
void rope_kernel(float* __restrict__ Q, float* __restrict__ K,
                 const int* __restrict__ pos_ids) {
    int gid = blockIdx.x * 256 + threadIdx.x;      // over NTOK*NHEAD*32
    int f   = gid & 31;
    int h   = (gid >> 5) & 15;
    int tok = gid >> 9;
    int pos = pos_ids[tok];
    float inv = powf(10000.0f, -(2.0f * (float)f) / 64.0f);
    float ang = (float)pos * inv;
    float c = cosf(ang), s = sinf(ang);
    size_t base = (size_t)tok * DMODEL + h * HDIM + 2 * f;
    float q0 = Q[base], q1 = Q[base + 1];
    Q[base]     = c * q0 - s * q1;
    Q[base + 1] = s * q0 + c * q1;
    float k0 = K[base], k1 = K[base + 1];
    K[base]     = c * k0 - s * k1;
    K[base + 1] = s * k0 + c * k1;
}

// ---------------- cache copy / scatter / gather ------------------------------
__global__ __launch_bounds__(256)
void copy_cache(float4* __restrict__ KC, float4* __restrict__ VC,
                const float4* __restrict__ lpk, const float4* __restrict__ lpv) {
    int i = blockIdx.x * 256 + threadIdx.x;        // over NTOK*1024
    KC[i] = lpk[i];
    VC[i] = lpv[i];
}

__global__ __launch_bounds__(256)
void scatter_kernel(float4* __restrict__ KC, float4* __restrict__ VC,
                    const float4* __restrict__ K, const float4* __restrict__ V,
                    const int* __restrict__ nkl,
                    const int* __restrict__ nvl) {
    int i = blockIdx.x * 256 + threadIdx.x;        // over NTOK*1024
    int off = i & 1023;
    int tok = i >> 10;
    int dk = nkl[tok];
    int dv = nvl[tok];
    KC[(size_t)dk * 1024 + off] = K[i];
    VC[(size_t)dv * 1024 + off] = V[i];
}

__global__ __launch_bounds__(256)
void gather_kernel(float4* __restrict__ Kg, float4* __restrict__ Vg,
                   const float4* __restrict__ KC, const float4* __restrict__ VC,
                   const int* __restrict__ vki,
                   const int* __restrict__ vvi) {
    int i = blockIdx.x * 256 + threadIdx.x;        // over NTOK*1024 (float4)
    int d4 = i & 63;
    int t  = (i >> 6) & 2047;
    int h  = (i >> 17) & 15;
    int b  = i >> 21;
    int sk = vki[b * S_LEN + t];
    int sv = vvi[b * S_LEN + t];
    Kg[i] = KC[(size_t)sk * 1024 + h * 64 + d4];
    Vg[i] = VC[(size_t)sv * 1024 + h * 64 + d4];
}

// ---------------- QK^T with causal mask + scale + attention_mask ------------
__global__ __launch_bounds__(256, 2)
void qk_gemm(const float* __restrict__ Qb, const float* __restrict__ Kg,
             const float* __restrict__ am, float* __restrict__ Sc) {
    const int tid = threadIdx.x;
    const int bh = blockIdx.z;
    const int b = bh >> 4, h = bh & 15;
    const int m0 = blockIdx.y * 128, n0 = blockIdx.x * 128;
    float* Cb = Sc + (size_t)bh * S_LEN * S_LEN;

    if (n0 > m0 + 127) {  // fully masked tile: constant fill, no compute
        float4 neg = make_float4(-1e30f, -1e30f, -1e30f, -1e30f);
        for (int i = tid; i < 128 * 32; i += 256) {
            int r = i >> 5;
            int c4 = (i & 31) << 2;
            *(float4*)&Cb[(size_t)(m0 + r) * S_LEN + n0 + c4] = neg;
        }
        return;
    }

    __shared__ __align__(16) float As[BK * 128];
    __shared__ __align__(16) float Bs[BK * 128];
    const float* Arow = Qb + (size_t)b * S_LEN * DMODEL + h * HDIM; // lda=DMODEL
    const float* Brow = Kg + (size_t)bh * S_LEN * HDIM;             // ldb=HDIM
    const int lr = tid >> 2;
    const int lc = (tid & 3) * 4;
    const int tm = (tid >> 4) * 8, tn = (tid & 15) * 8;
    unsigned long long acc[8][4];
#pragma unroll
    for (int i = 0; i < 8; i++)
#pragma unroll
        for (int j = 0; j < 4; j++) acc[i][j] = 0ULL;

    for (int k0 = 0; k0 < HDIM; k0 += BK) {
#pragma unroll
        for (int i = 0; i < 2; i++) {
            int r = lr + i * 64;
            float4 a = *(const float4*)&Arow[(size_t)(m0 + r) * DMODEL + k0 + lc];
            As[(lc + 0) * 128 + r] = a.x; As[(lc + 1) * 128 + r] = a.y;
            As[(lc + 2) * 128 + r] = a.z; As[(lc + 3) * 128 + r] = a.w;
            float4 bb = *(const float4*)&Brow[(size_t)(n0 + r) * HDIM + k0 + lc];
            Bs[(lc + 0) * 128 + r] = bb.x; Bs[(lc + 1) * 128 + r] = bb.y;
            Bs[(lc + 2) * 128 + r] = bb.z; Bs[(lc + 3) * 128 + r] = bb.w;
        }
        __syncthreads();
        mm8x8(As, Bs, tm, tn, acc);
        __syncthreads();
    }

    const float scale = 1.0f / 16.0f;
#pragma unroll
    for (int i = 0; i < 8; i++) {
        float c[8];
        unpack2(acc[i][0], c[0], c[1]); unpack2(acc[i][1], c[2], c[3]);
        unpack2(acc[i][2], c[4], c[5]); unpack2(acc[i][3], c[6], c[7]);
        int m = m0 + tm + i;
        float v[8];
#pragma unroll
        for (int j = 0; j < 8; j++) {
            int n = n0 + tn + j;
            v[j] = (n <= m) ? (c[j] * scale + am[b * S_LEN + n]) : -1e30f;
        }
        float4* p = (float4*)&Cb[(size_t)m * S_LEN + n0 + tn];
        p[0] = make_float4(v[0], v[1], v[2], v[3]);
        p[1] = make_float4(v[4], v[5], v[6], v[7]);
    }
}

// ---------------- row softmax over 2048 keys --------------------------------
__global__ __launch_bounds__(256)
void softmax_kernel(float* __restrict__ Sc) {
    __shared__ float sh[8];
    const size_t base = (size_t)blockIdx.x * S_LEN;
    const int tid = threadIdx.x;
    const int lane = tid & 31, wid = tid >> 5;
    float v[8];
    float m = -INFINITY;
#pragma unroll
    for (int i = 0; i < 8; i++) {
        v[i] = Sc[base + tid + i * 256];
        m = fmaxf(m, v[i]);
    }
#pragma unroll
    for (int o = 16; o; o >>= 1) m = fmaxf(m, __shfl_xor_sync(0xffffffffu, m, o));
    if (lane == 0) sh[wid] = m;
    __syncthreads();
    float mall = sh[0];
#pragma unroll
    for (int w = 1; w < 8; w++) mall = fmaxf(mall, sh[w]);
    __syncthreads();
    float s = 0.f;
#pragma unroll
    for (int i = 0; i < 8; i++) {
        v[i] = __expf(v[i] - mall);
        s += v[i];
    }
#pragma unroll
    for (int o = 16; o; o >>= 1) s += __shfl_xor_sync(0xffffffffu, s, o);
    if (lane == 0) sh[wid] = s;
    __syncthreads();
    float sall = 0.f;
#pragma unroll
    for (int w = 0; w < 8; w++) sall += sh[w];
    float inv = 1.0f / sall;
#pragma unroll
    for (int i = 0; i < 8; i++) Sc[base + tid + i * 256] = v[i] * inv;
}

// ---------------- PV GEMM (NN): O[b,s,h,:] = P * V --------------------------
__global__ __launch_bounds__(256, 2)
void pv_gemm(const float* __restrict__ Sc, const float* __restrict__ Vg,
             float* __restrict__ O) {
    __shared__ __align__(16) float As[BK * 128];
    __shared__ __align__(16) float Bs[BK * 128];
    const int tid = threadIdx.x;
    const int bh = blockIdx.z;
    const int b = bh >> 4, h = bh & 15;
    const int m0 = blockIdx.y * 128, n0 = blockIdx.x * 128;
    const float* A  = Sc + (size_t)bh * S_LEN * S_LEN;   // [m][k], lda=S_LEN
    const float* Bv = Vg + (size_t)bh * S_LEN * HDIM;    // [k][n], ldb=HDIM
    const int lr = tid >> 2;
    const int lc = (tid & 3) * 4;
    const int r2 = tid >> 4;           // 0..15 for Bs direct load
    const int c0 = (tid & 15) * 8;
    const int tm = (tid >> 4) * 8, tn = (tid & 15) * 8;
    unsigned long long acc[8][4];
#pragma unroll
    for (int i = 0; i < 8; i++)
#pragma unroll
        for (int j = 0; j < 4; j++) acc[i][j] = 0ULL;

    const int kmax = m0 + 128;  // causal: P[m][k]==0 for k>m
    for (int k0 = 0; k0 < kmax; k0 += BK) {
#pragma unroll
        for (int i = 0; i < 2; i++) {
            int r = lr + i * 64;
            float4 a = *(const float4*)&A[(size_t)(m0 + r) * S_LEN + k0 + lc];
            As[(lc + 0) * 128 + r] = a.x; As[(lc + 1) * 128 + r] = a.y;
            As[(lc + 2) * 128 + r] = a.z; As[(lc + 3) * 128 + r] = a.w;
        }
        float4 b0 = *(const float4*)&Bv[(size_t)(k0 + r2) * HDIM + n0 + c0];
        float4 b1 = *(const float4*)&Bv[(size_t)(k0 + r2) * HDIM + n0 + c0 + 4];
        *(float4*)&Bs[r2 * 128 + c0]     = b0;
        *(float4*)&Bs[r2 * 128 + c0 + 4] = b1;
        __syncthreads();
        mm8x8(As, Bs, tm, tn, acc);
        __syncthreads();
    }
#pragma unroll
    for (int i = 0; i < 8; i++) {
        float c[8];
        unpack2(acc[i][0], c[0], c[1]); unpack2(acc[i][1], c[2], c[3]);
        unpack2(acc[i][2], c[4], c[5]); unpack2(acc[i][3], c[6], c[7]);
        size_t tok = (size_t)b * S_LEN + (m0 + tm + i);
        float4* p = (float4*)&O[tok * DMODEL + h * HDIM + n0 + tn];
        p[0] = make_float4(c[0], c[1], c[2], c[3]);
        p[1] = make_float4(c[4], c[5], c[6], c[7]);
    }
}

// ---------------- host launcher ---------------------------------------------
extern "C" void kernel_launch(void* const* d_in, const int* in_sizes, int n_in,
                              void* d_out, int out_size) {
    (void)in_sizes; (void)n_in; (void)out_size;
    const float* hs  = (const float*)d_in[0];
    const float* Wq  = (const float*)d_in[1];
    const float* Wk  = (const float*)d_in[2];
    const float* Wv  = (const float*)d_in[3];
    const float* Wo  = (const float*)d_in[4];
    const float* lpk = (const float*)d_in[5];
    const float* lpv = (const float*)d_in[6];
    const float* am  = (const float*)d_in[7];
    const unsigned int* pos_raw = (const unsigned int*)d_in[8];
    const unsigned int* nkl_raw = (const unsigned int*)d_in[9];
    const unsigned int* nvl_raw = (const unsigned int*)d_in[10];
    const unsigned int* vki_raw = (const unsigned int*)d_in[11];
    const unsigned int* vvi_raw = (const unsigned int*)d_in[12];
    float* out = (float*)d_out;

    float *Q, *K, *V, *KC, *VC, *Kg, *Vg, *O, *Sc;
    __nv_bfloat16 *Xh, *Xl, *Wh, *Wl;
    int* idx;
    cudaGetSymbolAddress((void**)&Q,  g_Q);
    cudaGetSymbolAddress((void**)&K,  g_K);
    cudaGetSymbolAddress((void**)&V,  g_V);
    cudaGetSymbolAddress((void**)&KC, g_KC);
    cudaGetSymbolAddress((void**)&VC, g_VC);
    cudaGetSymbolAddress((void**)&Kg, g_Kg);
    cudaGetSymbolAddress((void**)&Vg, g_Vg);
    cudaGetSymbolAddress((void**)&O,  g_O);
    cudaGetSymbolAddress((void**)&Sc, g_Sc);
    cudaGetSymbolAddress((void**)&idx, g_idx);
    cudaGetSymbolAddress((void**)&Xh, g_Xh);
    cudaGetSymbolAddress((void**)&Xl, g_Xl);
    cudaGetSymbolAddress((void**)&Wh, g_Wh);
    cudaGetSymbolAddress((void**)&Wl, g_Wl);
    int* pos = idx + 0 * NTOK;
    int* nkl = idx + 1 * NTOK;
    int* nvl = idx + 2 * NTOK;
    int* vki = idx + 3 * NTOK;
    int* vvi = idx + 4 * NTOK;

    cudaFuncSetAttribute(gemm_split_mma, cudaFuncAttributeMaxDynamicSharedMemorySize,
                         GEMM_SMEM);

    // normalize index dtypes (int64-declared arrays may arrive as int32)
    conv_idx_kernel<<<16, 256>>>(pos_raw, pos, NTOK);
    conv_idx_kernel<<<16, 256>>>(nkl_raw, nkl, NTOK);
    conv_idx_kernel<<<16, 256>>>(nvl_raw, nvl, NTOK);
    conv_idx_kernel<<<16, 256>>>(vki_raw, vki, NTOK);
    conv_idx_kernel<<<16, 256>>>(vvi_raw, vvi, NTOK);

    const dim3 ggrid(DMODEL / GBN, DMODEL / GBM);       // (16, 32)
    const int CONV_BLOCKS = (NTOK * DMODEL / 4) / 256;  // 16384

    // ---- projections on tensor cores (bf16 split, mma.sync) ----
    conv_split_kernel<<<CONV_BLOCKS, 256>>>((const float4*)hs,
                                            (__nv_bfloat162*)Xh, (__nv_bfloat162*)Xl);
    conv_split_kernel<<<CONV_BLOCKS, 256>>>((const float4*)Wq,
                                            (__nv_bfloat162*)Wh, (__nv_bfloat162*)Wl);
    gemm_split_mma<<<ggrid, 256, GEMM_SMEM>>>(Xh, Xl, Wh, Wl, Q);
    conv_split_kernel<<<CONV_BLOCKS, 256>>>((const float4*)Wk,
                                            (__nv_bfloat162*)Wh, (__nv_bfloat162*)Wl);
    gemm_split_mma<<<ggrid, 256, GEMM_SMEM>>>(Xh, Xl, Wh, Wl, K);
    conv_split_kernel<<<CONV_BLOCKS, 256>>>((const float4*)Wv,
                                            (__nv_bfloat162*)Wh, (__nv_bfloat162*)Wl);
    gemm_split_mma<<<ggrid, 256, GEMM_SMEM>>>(Xh, Xl, Wh, Wl, V);

    rope_kernel<<<8192, 256>>>(Q, K, pos);

    copy_cache<<<16384, 256>>>((float4*)KC, (float4*)VC,
                               (const float4*)lpk, (const float4*)lpv);
    scatter_kernel<<<16384, 256>>>((float4*)KC, (float4*)VC,
                                   (const float4*)K, (const float4*)V, nkl, nvl);
    gather_kernel<<<16384, 256>>>((float4*)Kg, (float4*)Vg,
                                  (const float4*)KC, (const float4*)VC, vki, vvi);

    qk_gemm<<<dim3(16, 16, 32), 256>>>(Q, Kg, am, Sc);
    softmax_kernel<<<65536, 256>>>(Sc);
    pv_gemm<<<dim3(2, 16, 32), 256>>>(Sc, Vg, O);

    // ---- output projection on tensor cores ----
    conv_split_kernel<<<CONV_BLOCKS, 256>>>((const float4*)O,
                                            (__nv_bfloat162*)Xh, (__nv_bfloat162*)Xl);
    conv_split_kernel<<<CONV_BLOCKS, 256>>>((const float4*)Wo,
                                            (__nv_bfloat162*)Wh, (__nv_bfloat162*)Wl);
    gemm_split_mma<<<ggrid, 256, GEMM_SMEM>>>(Xh, Xl, Wh, Wl, out);
}

// round 6
// speedup vs baseline: 2.4533x; 1.1992x over previous
#include <cuda_runtime.h>
#include <cuda_bf16.h>
#include <math.h>
#include <stdint.h>

// Problem constants (fixed by the dataset)
#define S_LEN 2048
#define NHEAD 16
#define HDIM  256
#define BATCH 2
#define DMODEL 4096
#define NTOK  4096              // BATCH * S_LEN
#define BH    32                // BATCH * NHEAD

// ---------------- scratch (device globals; no allocations allowed) ----------
__device__ float g_Q [(size_t)NTOK * DMODEL];
__device__ float g_K [(size_t)NTOK * DMODEL];
__device__ float g_V [(size_t)NTOK * DMODEL];
__device__ float g_KC[(size_t)NTOK * DMODEL];
__device__ float g_VC[(size_t)NTOK * DMODEL];
__device__ float g_O [(size_t)NTOK * DMODEL];   // [B,S,H,HD]
__device__ float g_Sc[(size_t)BH * S_LEN * S_LEN]; // fp32 scores
__device__ int   g_idx[5][NTOK];
// bf16 split buffers
__device__ __nv_bfloat16 g_Xh[(size_t)NTOK * DMODEL];   // hs / Q / O splits
__device__ __nv_bfloat16 g_Xl[(size_t)NTOK * DMODEL];
__device__ __nv_bfloat16 g_Wh[(size_t)DMODEL * DMODEL];
__device__ __nv_bfloat16 g_Wl[(size_t)DMODEL * DMODEL];
__device__ __nv_bfloat16 g_Kgh[(size_t)NTOK * DMODEL];  // gathered K split [BH][S][HD]
__device__ __nv_bfloat16 g_Kgl[(size_t)NTOK * DMODEL];
__device__ __nv_bfloat16 g_Vth[(size_t)NTOK * DMODEL];  // V^T split: [BH][HD][S]
__device__ __nv_bfloat16 g_Vtl[(size_t)NTOK * DMODEL];
__device__ __nv_bfloat16 g_Ph[(size_t)BH * S_LEN * S_LEN];  // prob split
__device__ __nv_bfloat16 g_Pl[(size_t)BH * S_LEN * S_LEN];

// ============================================================================
// helpers
// ============================================================================
__device__ __forceinline__ uint32_t smem_u32(const void* p) {
    uint32_t a;
    asm("{ .reg .u64 t; cvta.to.shared.u64 t, %1; cvt.u32.u64 %0, t; }"
        : "=r"(a) : "l"(p));
    return a;
}
__device__ __forceinline__ void cp_async16(uint32_t dst, const void* src) {
    asm volatile("cp.async.cg.shared.global [%0], [%1], 16;"
                 :: "r"(dst), "l"(src) : "memory");
}
__device__ __forceinline__ void cp_commit() {
    asm volatile("cp.async.commit_group;" ::: "memory");
}
__device__ __forceinline__ void cp_wait1() {
    asm volatile("cp.async.wait_group 1;" ::: "memory");
}
__device__ __forceinline__ void mma_bf16(float* d, const uint32_t* a, const uint32_t* b) {
    asm volatile(
        "mma.sync.aligned.m16n8k16.row.col.f32.bf16.bf16.f32 "
        "{%0,%1,%2,%3}, {%4,%5,%6,%7}, {%8,%9}, {%0,%1,%2,%3};"
        : "+f"(d[0]), "+f"(d[1]), "+f"(d[2]), "+f"(d[3])
        : "r"(a[0]), "r"(a[1]), "r"(a[2]), "r"(a[3]), "r"(b[0]), "r"(b[1]));
}

// ============================================================================
// shared bf16-split mma core: CTA tile 128(M) x 256(N) x 32(K), 8 warps (2x4),
// warp tile 64x64, 3-stage cp.async pipeline, 80B-padded smem rows.
// Computes acc = Ah*Bh^T + Ah*Bl^T + Al*Bh^T over kiters*32 K elements.
// ============================================================================
#define GBM 128
#define GBN 256
#define GBK 32
#define ROWB 80
#define SM_A_SZ (GBM * ROWB)            // 10240
#define SM_B_SZ (GBN * ROWB)            // 20480
#define OFF_AH 0
#define OFF_AL SM_A_SZ
#define OFF_BH (2 * SM_A_SZ)
#define OFF_BL (2 * SM_A_SZ + SM_B_SZ)
#define STAGE_B (2 * SM_A_SZ + 2 * SM_B_SZ)  // 61440
#define PIPE 3
#define GEMM_SMEM (PIPE * STAGE_B)      // 184320

__device__ __forceinline__ void gemm_split_core(
    const __nv_bfloat16* __restrict__ Ah, const __nv_bfloat16* __restrict__ Al,
    const __nv_bfloat16* __restrict__ Bh, const __nv_bfloat16* __restrict__ Bl,
    int64_t lda, int64_t ldb, int kiters,
    char* sm, float acc[4][8][4])
{
    const uint32_t sbase = smem_u32(sm);
    const int tid  = threadIdx.x;
    const int lane = tid & 31;
    const int g = lane >> 2, t = lane & 3;
    const int wid = tid >> 5;
    const int wm = wid >> 2, wn = wid & 3;

#pragma unroll
    for (int i = 0; i < 4; i++)
#pragma unroll
        for (int j = 0; j < 8; j++)
#pragma unroll
            for (int r = 0; r < 4; r++) acc[i][j][r] = 0.f;

    // per-thread cp.async chunk setup: 12 x 16B per stage
    const __nv_bfloat16* src[12];
    uint32_t dst[12];
#pragma unroll
    for (int q = 0; q < 12; q++) {
        int c = tid + q * 256;
        if (c < 1024) {
            int sp = c >> 9; int idx = c & 511;
            int row = idx >> 2, kc = idx & 3;
            src[q] = (sp ? Al : Ah) + (int64_t)row * lda + kc * 8;
            dst[q] = (sp ? OFF_AL : OFF_AH) + row * ROWB + kc * 16;
        } else {
            int c2 = c - 1024; int sp = c2 >> 10; int idx = c2 & 1023;
            int row = idx >> 2, kc = idx & 3;
            src[q] = (sp ? Bl : Bh) + (int64_t)row * ldb + kc * 8;
            dst[q] = (sp ? OFF_BL : OFF_BH) + row * ROWB + kc * 16;
        }
    }
    auto issue = [&](int s) {
        uint32_t stg = sbase + s * STAGE_B;
#pragma unroll
        for (int q = 0; q < 12; q++) {
            cp_async16(stg + dst[q], src[q]);
            src[q] += GBK;
        }
    };

    issue(0); cp_commit();
    issue(1); cp_commit();

    for (int it = 0; it < kiters; it++) {
        cp_wait1();
        __syncthreads();
        const char* stg = sm + (it % PIPE) * STAGE_B;

#pragma unroll
        for (int ks = 0; ks < 2; ks++) {
            const int kb = ks * 32 + t * 4;
            uint32_t ah[4][4], al[4][4], bh[8][2], bl[8][2];
#pragma unroll
            for (int i = 0; i < 4; i++) {
                int r0 = wm * 64 + i * 16 + g;
                const char* p = stg + OFF_AH + r0 * ROWB + kb;
                ah[i][0] = *(const uint32_t*)(p);
                ah[i][1] = *(const uint32_t*)(p + 8 * ROWB);
                ah[i][2] = *(const uint32_t*)(p + 16);
                ah[i][3] = *(const uint32_t*)(p + 8 * ROWB + 16);
            }
#pragma unroll
            for (int j = 0; j < 8; j++) {
                int n = wn * 64 + j * 8 + g;
                const char* p = stg + OFF_BH + n * ROWB + kb;
                bh[j][0] = *(const uint32_t*)(p);
                bh[j][1] = *(const uint32_t*)(p + 16);
            }
#pragma unroll
            for (int i = 0; i < 4; i++)
#pragma unroll
                for (int j = 0; j < 8; j++) mma_bf16(acc[i][j], ah[i], bh[j]);

#pragma unroll
            for (int j = 0; j < 8; j++) {
                int n = wn * 64 + j * 8 + g;
                const char* p = stg + OFF_BL + n * ROWB + kb;
                bl[j][0] = *(const uint32_t*)(p);
                bl[j][1] = *(const uint32_t*)(p + 16);
            }
#pragma unroll
            for (int i = 0; i < 4; i++)
#pragma unroll
                for (int j = 0; j < 8; j++) mma_bf16(acc[i][j], ah[i], bl[j]);

#pragma unroll
            for (int i = 0; i < 4; i++) {
                int r0 = wm * 64 + i * 16 + g;
                const char* p = stg + OFF_AL + r0 * ROWB + kb;
                al[i][0] = *(const uint32_t*)(p);
                al[i][1] = *(const uint32_t*)(p + 8 * ROWB);
                al[i][2] = *(const uint32_t*)(p + 16);
                al[i][3] = *(const uint32_t*)(p + 8 * ROWB + 16);
            }
#pragma unroll
            for (int i = 0; i < 4; i++)
#pragma unroll
                for (int j = 0; j < 8; j++) mma_bf16(acc[i][j], al[i], bh[j]);
        }

        if (it + 2 < kiters) issue((it + 2) % PIPE);
        cp_commit();
    }
}

// ---------------- projection GEMM: C = A * W^T (4096^3) ----------------------
__global__ __launch_bounds__(256, 1)
void gemm_proj(const __nv_bfloat16* __restrict__ Agh, const __nv_bfloat16* __restrict__ Agl,
               const __nv_bfloat16* __restrict__ Bgh, const __nv_bfloat16* __restrict__ Bgl,
               float* __restrict__ C) {
    extern __shared__ __align__(16) char sm[];
    const int m0 = blockIdx.y * GBM, n0 = blockIdx.x * GBN;
    float acc[4][8][4];
    gemm_split_core(Agh + (size_t)m0 * DMODEL, Agl + (size_t)m0 * DMODEL,
                    Bgh + (size_t)n0 * DMODEL, Bgl + (size_t)n0 * DMODEL,
                    DMODEL, DMODEL, DMODEL / GBK, sm, acc);
    const int lane = threadIdx.x & 31, wid = threadIdx.x >> 5;
    const int g = lane >> 2, t = lane & 3;
    const int wm = wid >> 2, wn = wid & 3;
#pragma unroll
    for (int i = 0; i < 4; i++) {
        int m = m0 + wm * 64 + i * 16 + g;
#pragma unroll
        for (int j = 0; j < 8; j++) {
            int n = n0 + wn * 64 + j * 8 + t * 2;
            *(float2*)&C[(size_t)m * DMODEL + n]       = make_float2(acc[i][j][0], acc[i][j][1]);
            *(float2*)&C[(size_t)(m + 8) * DMODEL + n] = make_float2(acc[i][j][2], acc[i][j][3]);
        }
    }
}

// ---------------- QK^T GEMM with causal mask + scale + attention mask -------
__global__ __launch_bounds__(256, 1)
void qk_mma(const __nv_bfloat16* __restrict__ Qh, const __nv_bfloat16* __restrict__ Ql,
            const __nv_bfloat16* __restrict__ Kh, const __nv_bfloat16* __restrict__ Kl,
            const float* __restrict__ am, float* __restrict__ Sc) {
    extern __shared__ __align__(16) char sm[];
    const int bh = blockIdx.z;
    const int b = bh >> 4, h = bh & 15;
    const int m0 = blockIdx.y * GBM, n0 = blockIdx.x * GBN;
    float* Cb = Sc + (size_t)bh * S_LEN * S_LEN;
    const int tid = threadIdx.x;

    if (n0 > m0 + (GBM - 1)) {      // fully masked tile: fill, no compute
        float4 neg = make_float4(-1e30f, -1e30f, -1e30f, -1e30f);
        for (int i = tid; i < GBM * (GBN / 4); i += 256) {
            int r = i / (GBN / 4);
            int c4 = (i % (GBN / 4)) * 4;
            *(float4*)&Cb[(size_t)(m0 + r) * S_LEN + n0 + c4] = neg;
        }
        return;
    }

    const size_t aoff = (size_t)b * S_LEN * DMODEL + (size_t)h * HDIM + (size_t)m0 * DMODEL;
    const size_t boff = (size_t)bh * S_LEN * HDIM + (size_t)n0 * HDIM;
    float acc[4][8][4];
    gemm_split_core(Qh + aoff, Ql + aoff, Kh + boff, Kl + boff,
                    DMODEL, HDIM, HDIM / GBK, sm, acc);

    const int lane = tid & 31, wid = tid >> 5;
    const int g = lane >> 2, t = lane & 3;
    const int wm = wid >> 2, wn = wid & 3;
    const float scale = 1.0f / 16.0f;
#pragma unroll
    for (int i = 0; i < 4; i++) {
        int m = m0 + wm * 64 + i * 16 + g;
#pragma unroll
        for (int j = 0; j < 8; j++) {
            int n = n0 + wn * 64 + j * 8 + t * 2;
            float amv0 = am[b * S_LEN + n], amv1 = am[b * S_LEN + n + 1];
            float v0 = (n     <= m) ? (acc[i][j][0] * scale + amv0) : -1e30f;
            float v1 = (n + 1 <= m) ? (acc[i][j][1] * scale + amv1) : -1e30f;
            float v2 = (n     <= m + 8) ? (acc[i][j][2] * scale + amv0) : -1e30f;
            float v3 = (n + 1 <= m + 8) ? (acc[i][j][3] * scale + amv1) : -1e30f;
            *(float2*)&Cb[(size_t)m * S_LEN + n]       = make_float2(v0, v1);
            *(float2*)&Cb[(size_t)(m + 8) * S_LEN + n] = make_float2(v2, v3);
        }
    }
}

// ---------------- PV GEMM: O[b,s,h,:] = P * V (causal-truncated K) ----------
__global__ __launch_bounds__(256, 1)
void pv_mma(const __nv_bfloat16* __restrict__ Ph, const __nv_bfloat16* __restrict__ Pl,
            const __nv_bfloat16* __restrict__ Vth, const __nv_bfloat16* __restrict__ Vtl,
            float* __restrict__ O) {
    extern __shared__ __align__(16) char sm[];
    const int bh = blockIdx.z;
    const int b = bh >> 4, h = bh & 15;
    const int m0 = blockIdx.y * GBM;     // n0 = 0 (N = HDIM = 256, one tile)
    const size_t aoff = (size_t)bh * S_LEN * S_LEN + (size_t)m0 * S_LEN;
    const size_t boff = (size_t)bh * HDIM * S_LEN;
    float acc[4][8][4];
    gemm_split_core(Ph + aoff, Pl + aoff, Vth + boff, Vtl + boff,
                    S_LEN, S_LEN, (m0 + GBM) / GBK, sm, acc);

    const int lane = threadIdx.x & 31, wid = threadIdx.x >> 5;
    const int g = lane >> 2, t = lane & 3;
    const int wm = wid >> 2, wn = wid & 3;
#pragma unroll
    for (int i = 0; i < 4; i++) {
        int m = m0 + wm * 64 + i * 16 + g;
        size_t tok0 = (size_t)b * S_LEN + m;
#pragma unroll
        for (int j = 0; j < 8; j++) {
            int n = wn * 64 + j * 8 + t * 2;
            *(float2*)&O[tok0 * DMODEL + h * HDIM + n]       = make_float2(acc[i][j][0], acc[i][j][1]);
            *(float2*)&O[(tok0 + 8) * DMODEL + h * HDIM + n] = make_float2(acc[i][j][2], acc[i][j][3]);
        }
    }
}

// ---------------- fp32 -> (bf16 hi, bf16 lo) split conversion ----------------
__global__ __launch_bounds__(256)
void conv_split_kernel(const float4* __restrict__ x,
                       __nv_bfloat162* __restrict__ hi,
                       __nv_bfloat162* __restrict__ lo) {
    int i = blockIdx.x * 256 + threadIdx.x;
    float4 v = x[i];
    __nv_bfloat16 h0 = __float2bfloat16(v.x);
    __nv_bfloat16 h1 = __float2bfloat16(v.y);
    __nv_bfloat16 h2 = __float2bfloat16(v.z);
    __nv_bfloat16 h3 = __float2bfloat16(v.w);
    __nv_bfloat16 l0 = __float2bfloat16(v.x - __bfloat162float(h0));
    __nv_bfloat16 l1 = __float2bfloat16(v.y - __bfloat162float(h1));
    __nv_bfloat16 l2 = __float2bfloat16(v.z - __bfloat162float(h2));
    __nv_bfloat16 l3 = __float2bfloat16(v.w - __bfloat162float(h3));
    hi[2 * i]     = __halves2bfloat162(h0, h1);
    hi[2 * i + 1] = __halves2bfloat162(h2, h3);
    lo[2 * i]     = __halves2bfloat162(l0, l1);
    lo[2 * i + 1] = __halves2bfloat162(l2, l3);
}

// ---------------- fused K gather + split: KC -> Kgh/Kgl [BH][S][HD] ----------
__global__ __launch_bounds__(256)
void kgather_split(const float4* __restrict__ KC,
                   const int* __restrict__ vki,
                   __nv_bfloat162* __restrict__ Kgh,
                   __nv_bfloat162* __restrict__ Kgl) {
    int i = blockIdx.x * 256 + threadIdx.x;       // over NTOK*1024 float4s
    int d4 = i & 63;
    int t  = (i >> 6) & 2047;
    int h  = (i >> 17) & 15;
    int b  = i >> 21;
    int sk = vki[b * S_LEN + t];
    float4 v = KC[(size_t)sk * 1024 + h * 64 + d4];
    __nv_bfloat16 h0 = __float2bfloat16(v.x);
    __nv_bfloat16 h1 = __float2bfloat16(v.y);
    __nv_bfloat16 h2 = __float2bfloat16(v.z);
    __nv_bfloat16 h3 = __float2bfloat16(v.w);
    __nv_bfloat16 l0 = __float2bfloat16(v.x - __bfloat162float(h0));
    __nv_bfloat16 l1 = __float2bfloat16(v.y - __bfloat162float(h1));
    __nv_bfloat16 l2 = __float2bfloat16(v.z - __bfloat162float(h2));
    __nv_bfloat16 l3 = __float2bfloat16(v.w - __bfloat162float(h3));
    size_t o = (size_t)i * 2;                     // same linear layout, bf16x2 units
    Kgh[o]     = __halves2bfloat162(h0, h1);
    Kgh[o + 1] = __halves2bfloat162(h2, h3);
    Kgl[o]     = __halves2bfloat162(l0, l1);
    Kgl[o + 1] = __halves2bfloat162(l2, l3);
}

// ---------------- fused V gather + transpose + split: VC -> Vt [BH][HD][S] ---
__global__ __launch_bounds__(256)
void vgather_trans_split(const float* __restrict__ VC,
                         const int* __restrict__ vvi,
                         __nv_bfloat16* __restrict__ Vth,
                         __nv_bfloat16* __restrict__ Vtl) {
    __shared__ float tile[32][33];
    const int bh = blockIdx.z;
    const int b = bh >> 4, h = bh & 15;
    const int s0 = blockIdx.x * 32, d0 = blockIdx.y * 32;
    const int tx = threadIdx.x & 31, ty = threadIdx.x >> 5;
#pragma unroll
    for (int r = 0; r < 32; r += 8) {
        int sv = vvi[b * S_LEN + s0 + ty + r];
        tile[ty + r][tx] = VC[(size_t)sv * DMODEL + h * HDIM + d0 + tx];
    }
    __syncthreads();
    __nv_bfloat16* dh = Vth + (size_t)bh * HDIM * S_LEN;
    __nv_bfloat16* dl = Vtl + (size_t)bh * HDIM * S_LEN;
#pragma unroll
    for (int r = 0; r < 32; r += 8) {
        float v = tile[tx][ty + r];
        __nv_bfloat16 hh = __float2bfloat16(v);
        __nv_bfloat16 ll = __float2bfloat16(v - __bfloat162float(hh));
        size_t o = (size_t)(d0 + ty + r) * S_LEN + s0 + tx;
        dh[o] = hh;
        dl[o] = ll;
    }
}

// ---------------- index dtype normalization ---------------------------------
__global__ __launch_bounds__(256)
void conv_idx_kernel(const unsigned int* __restrict__ raw,
                     int* __restrict__ out, int n) {
    bool is64 = (raw[1] == 0u) && (raw[3] == 0u) && (raw[5] == 0u);
    int i = blockIdx.x * 256 + threadIdx.x;
    if (i < n) out[i] = is64 ? (int)raw[2 * i] : (int)raw[i];
}

// ---------------- RoPE (first 64 dims of each head, in place on Q and K) ----
__global__ __launch_bounds__(256)
void rope_kernel(float* __restrict__ Q, float* __restrict__ K,
                 const int* __restrict__ pos_ids) {
    int gid = blockIdx.x * 256 + threadIdx.x;      // over NTOK*NHEAD*32
    int f   = gid & 31;
    int h   = (gid >> 5) & 15;
    int tok = gid >> 9;
    int pos = pos_ids[tok];
    float inv = powf(10000.0f, -(2.0f * (float)f) / 64.0f);
    float ang = (float)pos * inv;
    float c = cosf(ang), s = sinf(ang);
    size_t base = (size_t)tok * DMODEL + h * HDIM + 2 * f;
    float q0 = Q[base], q1 = Q[base + 1];
    Q[base]     = c * q0 - s * q1;
    Q[base + 1] = s * q0 + c * q1;
    float k0 = K[base], k1 = K[base + 1];
    K[base]     = c * k0 - s * k1;
    K[base + 1] = s * k0 + c * k1;
}

// ---------------- cache copy / scatter ---------------------------------------
__global__ __launch_bounds__(256)
void copy_cache(float4* __restrict__ KC, float4* __restrict__ VC,
                const float4* __restrict__ lpk, const float4* __restrict__ lpv) {
    int i = blockIdx.x * 256 + threadIdx.x;
    KC[i] = lpk[i];
    VC[i] = lpv[i];
}

__global__ __launch_bounds__(256)
void scatter_kernel(float4* __restrict__ KC, float4* __restrict__ VC,
                    const float4* __restrict__ K, const float4* __restrict__ V,
                    const int* __restrict__ nkl,
                    const int* __restrict__ nvl) {
    int i = blockIdx.x * 256 + threadIdx.x;
    int off = i & 1023;
    int tok = i >> 10;
    int dk = nkl[tok];
    int dv = nvl[tok];
    KC[(size_t)dk * 1024 + off] = K[i];
    VC[(size_t)dv * 1024 + off] = V[i];
}

// ---------------- row softmax -> bf16 hi/lo prob splits ----------------------
__global__ __launch_bounds__(256)
void softmax_split(const float* __restrict__ Sc,
                   __nv_bfloat16* __restrict__ Ph,
                   __nv_bfloat16* __restrict__ Pl) {
    __shared__ float sh[8];
    const size_t base = (size_t)blockIdx.x * S_LEN;
    const int tid = threadIdx.x;
    const int lane = tid & 31, wid = tid >> 5;
    float v[8];
    float m = -INFINITY;
#pragma unroll
    for (int i = 0; i < 8; i++) {
        v[i] = Sc[base + tid + i * 256];
        m = fmaxf(m, v[i]);
    }
#pragma unroll
    for (int o = 16; o; o >>= 1) m = fmaxf(m, __shfl_xor_sync(0xffffffffu, m, o));
    if (lane == 0) sh[wid] = m;
    __syncthreads();
    float mall = sh[0];
#pragma unroll
    for (int w = 1; w < 8; w++) mall = fmaxf(mall, sh[w]);
    __syncthreads();
    float s = 0.f;
#pragma unroll
    for (int i = 0; i < 8; i++) {
        v[i] = __expf(v[i] - mall);
        s += v[i];
    }
#pragma unroll
    for (int o = 16; o; o >>= 1) s += __shfl_xor_sync(0xffffffffu, s, o);
    if (lane == 0) sh[wid] = s;
    __syncthreads();
    float sall = 0.f;
#pragma unroll
    for (int w = 0; w < 8; w++) sall += sh[w];
    float inv = 1.0f / sall;
#pragma unroll
    for (int i = 0; i < 8; i++) {
        float p = v[i] * inv;
        __nv_bfloat16 h = __float2bfloat16(p);
        Ph[base + tid + i * 256] = h;
        Pl[base + tid + i * 256] = __float2bfloat16(p - __bfloat162float(h));
    }
}

// ---------------- host launcher ---------------------------------------------
extern "C" void kernel_launch(void* const* d_in, const int* in_sizes, int n_in,
                              void* d_out, int out_size) {
    (void)in_sizes; (void)n_in; (void)out_size;
    const float* hs  = (const float*)d_in[0];
    const float* Wq  = (const float*)d_in[1];
    const float* Wk  = (const float*)d_in[2];
    const float* Wv  = (const float*)d_in[3];
    const float* Wo  = (const float*)d_in[4];
    const float* lpk = (const float*)d_in[5];
    const float* lpv = (const float*)d_in[6];
    const float* am  = (const float*)d_in[7];
    const unsigned int* pos_raw = (const unsigned int*)d_in[8];
    const unsigned int* nkl_raw = (const unsigned int*)d_in[9];
    const unsigned int* nvl_raw = (const unsigned int*)d_in[10];
    const unsigned int* vki_raw = (const unsigned int*)d_in[11];
    const unsigned int* vvi_raw = (const unsigned int*)d_in[12];
    float* out = (float*)d_out;

    float *Q, *K, *V, *KC, *VC, *O, *Sc;
    __nv_bfloat16 *Xh, *Xl, *Wh, *Wl, *Kgh, *Kgl, *Vth, *Vtl, *Ph, *Pl;
    int* idx;
    cudaGetSymbolAddress((void**)&Q,  g_Q);
    cudaGetSymbolAddress((void**)&K,  g_K);
    cudaGetSymbolAddress((void**)&V,  g_V);
    cudaGetSymbolAddress((void**)&KC, g_KC);
    cudaGetSymbolAddress((void**)&VC, g_VC);
    cudaGetSymbolAddress((void**)&O,  g_O);
    cudaGetSymbolAddress((void**)&Sc, g_Sc);
    cudaGetSymbolAddress((void**)&idx, g_idx);
    cudaGetSymbolAddress((void**)&Xh, g_Xh);
    cudaGetSymbolAddress((void**)&Xl, g_Xl);
    cudaGetSymbolAddress((void**)&Wh, g_Wh);
    cudaGetSymbolAddress((void**)&Wl, g_Wl);
    cudaGetSymbolAddress((void**)&Kgh, g_Kgh);
    cudaGetSymbolAddress((void**)&Kgl, g_Kgl);
    cudaGetSymbolAddress((void**)&Vth, g_Vth);
    cudaGetSymbolAddress((void**)&Vtl, g_Vtl);
    cudaGetSymbolAddress((void**)&Ph, g_Ph);
    cudaGetSymbolAddress((void**)&Pl, g_Pl);
    int* pos = idx + 0 * NTOK;
    int* nkl = idx + 1 * NTOK;
    int* nvl = idx + 2 * NTOK;
    int* vki = idx + 3 * NTOK;
    int* vvi = idx + 4 * NTOK;

    cudaFuncSetAttribute(gemm_proj, cudaFuncAttributeMaxDynamicSharedMemorySize, GEMM_SMEM);
    cudaFuncSetAttribute(qk_mma,    cudaFuncAttributeMaxDynamicSharedMemorySize, GEMM_SMEM);
    cudaFuncSetAttribute(pv_mma,    cudaFuncAttributeMaxDynamicSharedMemorySize, GEMM_SMEM);

    conv_idx_kernel<<<16, 256>>>(pos_raw, pos, NTOK);
    conv_idx_kernel<<<16, 256>>>(nkl_raw, nkl, NTOK);
    conv_idx_kernel<<<16, 256>>>(nvl_raw, nvl, NTOK);
    conv_idx_kernel<<<16, 256>>>(vki_raw, vki, NTOK);
    conv_idx_kernel<<<16, 256>>>(vvi_raw, vvi, NTOK);

    const dim3 ggrid(DMODEL / GBN, DMODEL / GBM);       // (16, 32)
    const int CONV_BLOCKS = (NTOK * DMODEL / 4) / 256;  // 16384

    // ---- QKV projections (tensor cores) ----
    conv_split_kernel<<<CONV_BLOCKS, 256>>>((const float4*)hs,
                                            (__nv_bfloat162*)Xh, (__nv_bfloat162*)Xl);
    conv_split_kernel<<<CONV_BLOCKS, 256>>>((const float4*)Wq,
                                            (__nv_bfloat162*)Wh, (__nv_bfloat162*)Wl);
    gemm_proj<<<ggrid, 256, GEMM_SMEM>>>(Xh, Xl, Wh, Wl, Q);
    conv_split_kernel<<<CONV_BLOCKS, 256>>>((const float4*)Wk,
                                            (__nv_bfloat162*)Wh, (__nv_bfloat162*)Wl);
    gemm_proj<<<ggrid, 256, GEMM_SMEM>>>(Xh, Xl, Wh, Wl, K);
    conv_split_kernel<<<CONV_BLOCKS, 256>>>((const float4*)Wv,
                                            (__nv_bfloat162*)Wh, (__nv_bfloat162*)Wl);
    gemm_proj<<<ggrid, 256, GEMM_SMEM>>>(Xh, Xl, Wh, Wl, V);

    rope_kernel<<<8192, 256>>>(Q, K, pos);

    copy_cache<<<16384, 256>>>((float4*)KC, (float4*)VC,
                               (const float4*)lpk, (const float4*)lpv);
    scatter_kernel<<<16384, 256>>>((float4*)KC, (float4*)VC,
                                   (const float4*)K, (const float4*)V, nkl, nvl);

    // ---- fused gather + split/transpose conversions ----
    kgather_split<<<16384, 256>>>((const float4*)KC, vki,
                                  (__nv_bfloat162*)Kgh, (__nv_bfloat162*)Kgl);
    vgather_trans_split<<<dim3(S_LEN / 32, HDIM / 32, BH), 256>>>(VC, vvi, Vth, Vtl);
    conv_split_kernel<<<CONV_BLOCKS, 256>>>((const float4*)Q,
                                            (__nv_bfloat162*)Xh, (__nv_bfloat162*)Xl);

    // ---- attention on tensor cores ----
    qk_mma<<<dim3(S_LEN / GBN, S_LEN / GBM, BH), 256, GEMM_SMEM>>>(
        Xh, Xl, Kgh, Kgl, am, Sc);
    softmax_split<<<BH * S_LEN, 256>>>(Sc, Ph, Pl);
    pv_mma<<<dim3(1, S_LEN / GBM, BH), 256, GEMM_SMEM>>>(Ph, Pl, Vth, Vtl, O);

    // ---- output projection ----
    conv_split_kernel<<<CONV_BLOCKS, 256>>>((const float4*)O,
                                            (__nv_bfloat162*)Xh, (__nv_bfloat162*)Xl);
    conv_split_kernel<<<CONV_BLOCKS, 256>>>((const float4*)Wo,
                                            (__nv_bfloat162*)Wh, (__nv_bfloat162*)Wl);
    gemm_proj<<<ggrid, 256, GEMM_SMEM>>>(Xh, Xl, Wh, Wl, out);
}

// round 7
// speedup vs baseline: 2.4813x; 1.0114x over previous
#include <cuda_runtime.h>
#include <cuda_bf16.h>
#include <math.h>
#include <stdint.h>

// Problem constants (fixed by the dataset)
#define S_LEN 2048
#define NHEAD 16
#define HDIM  256
#define BATCH 2
#define DMODEL 4096
#define NTOK  4096              // BATCH * S_LEN
#define BH    32                // BATCH * NHEAD

// ---------------- scratch (device globals; no allocations allowed) ----------
__device__ float g_K [(size_t)NTOK * DMODEL];   // post-RoPE K (fp32, cache source)
__device__ float g_V [(size_t)NTOK * DMODEL];
__device__ float g_Sc[(size_t)BH * S_LEN * S_LEN]; // fp32 scores
__device__ int   g_idx[5][NTOK];
__device__ int   g_inv[2][NTOK];                // inverse cache maps (k, v)
// bf16 split buffers
__device__ __nv_bfloat16 g_Xh[(size_t)NTOK * DMODEL];   // hs splits, later O splits
__device__ __nv_bfloat16 g_Xl[(size_t)NTOK * DMODEL];
__device__ __nv_bfloat16 g_Qh[(size_t)NTOK * DMODEL];   // post-RoPE Q splits
__device__ __nv_bfloat16 g_Ql[(size_t)NTOK * DMODEL];
__device__ __nv_bfloat16 g_Wqh[(size_t)DMODEL * DMODEL];
__device__ __nv_bfloat16 g_Wql[(size_t)DMODEL * DMODEL];
__device__ __nv_bfloat16 g_Wkh[(size_t)DMODEL * DMODEL];
__device__ __nv_bfloat16 g_Wkl[(size_t)DMODEL * DMODEL];
__device__ __nv_bfloat16 g_Wvh[(size_t)DMODEL * DMODEL];
__device__ __nv_bfloat16 g_Wvl[(size_t)DMODEL * DMODEL];
__device__ __nv_bfloat16 g_Woh[(size_t)DMODEL * DMODEL];
__device__ __nv_bfloat16 g_Wol[(size_t)DMODEL * DMODEL];
__device__ __nv_bfloat16 g_Kgh[(size_t)NTOK * DMODEL];  // gathered K split [BH][S][HD]
__device__ __nv_bfloat16 g_Kgl[(size_t)NTOK * DMODEL];
__device__ __nv_bfloat16 g_Vth[(size_t)NTOK * DMODEL];  // V^T split: [BH][HD][S]
__device__ __nv_bfloat16 g_Vtl[(size_t)NTOK * DMODEL];
__device__ __nv_bfloat16 g_Ph[(size_t)BH * S_LEN * S_LEN];  // prob split
__device__ __nv_bfloat16 g_Pl[(size_t)BH * S_LEN * S_LEN];

// ============================================================================
// helpers
// ============================================================================
__device__ __forceinline__ uint32_t smem_u32(const void* p) {
    uint32_t a;
    asm("{ .reg .u64 t; cvta.to.shared.u64 t, %1; cvt.u32.u64 %0, t; }"
        : "=r"(a) : "l"(p));
    return a;
}
__device__ __forceinline__ void cp_async16(uint32_t dst, const void* src) {
    asm volatile("cp.async.cg.shared.global [%0], [%1], 16;"
                 :: "r"(dst), "l"(src) : "memory");
}
__device__ __forceinline__ void cp_commit() {
    asm volatile("cp.async.commit_group;" ::: "memory");
}
__device__ __forceinline__ void cp_wait1() {
    asm volatile("cp.async.wait_group 1;" ::: "memory");
}
__device__ __forceinline__ void mma_bf16(float* d, const uint32_t* a, const uint32_t* b) {
    asm volatile(
        "mma.sync.aligned.m16n8k16.row.col.f32.bf16.bf16.f32 "
        "{%0,%1,%2,%3}, {%4,%5,%6,%7}, {%8,%9}, {%0,%1,%2,%3};"
        : "+f"(d[0]), "+f"(d[1]), "+f"(d[2]), "+f"(d[3])
        : "r"(a[0]), "r"(a[1]), "r"(a[2]), "r"(a[3]), "r"(b[0]), "r"(b[1]));
}
__device__ __forceinline__ __nv_bfloat162 split_hi2(float a, float b,
                                                    __nv_bfloat162& lo) {
    __nv_bfloat16 h0 = __float2bfloat16(a);
    __nv_bfloat16 h1 = __float2bfloat16(b);
    lo = __halves2bfloat162(__float2bfloat16(a - __bfloat162float(h0)),
                            __float2bfloat16(b - __bfloat162float(h1)));
    return __halves2bfloat162(h0, h1);
}

// ============================================================================
// shared bf16-split mma core: CTA tile 128(M) x 256(N) x 32(K), 8 warps (2x4),
// warp tile 64x64, 3-stage cp.async pipeline, 80B-padded smem rows.
// acc = Ah*Bh^T + Ah*Bl^T + Al*Bh^T over kiters*32 K elements.
// ============================================================================
#define GBM 128
#define GBN 256
#define GBK 32
#define ROWB 80
#define SM_A_SZ (GBM * ROWB)            // 10240
#define SM_B_SZ (GBN * ROWB)            // 20480
#define OFF_AH 0
#define OFF_AL SM_A_SZ
#define OFF_BH (2 * SM_A_SZ)
#define OFF_BL (2 * SM_A_SZ + SM_B_SZ)
#define STAGE_B (2 * SM_A_SZ + 2 * SM_B_SZ)  // 61440
#define PIPE 3
#define GEMM_SMEM (PIPE * STAGE_B)      // 184320

__device__ __forceinline__ void gemm_split_core(
    const __nv_bfloat16* __restrict__ Ah, const __nv_bfloat16* __restrict__ Al,
    const __nv_bfloat16* __restrict__ Bh, const __nv_bfloat16* __restrict__ Bl,
    int64_t lda, int64_t ldb, int kiters,
    char* sm, float acc[4][8][4])
{
    const uint32_t sbase = smem_u32(sm);
    const int tid  = threadIdx.x;
    const int lane = tid & 31;
    const int g = lane >> 2, t = lane & 3;
    const int wid = tid >> 5;
    const int wm = wid >> 2, wn = wid & 3;

#pragma unroll
    for (int i = 0; i < 4; i++)
#pragma unroll
        for (int j = 0; j < 8; j++)
#pragma unroll
            for (int r = 0; r < 4; r++) acc[i][j][r] = 0.f;

    const __nv_bfloat16* src[12];
    uint32_t dst[12];
#pragma unroll
    for (int q = 0; q < 12; q++) {
        int c = tid + q * 256;
        if (c < 1024) {
            int sp = c >> 9; int idx = c & 511;
            int row = idx >> 2, kc = idx & 3;
            src[q] = (sp ? Al : Ah) + (int64_t)row * lda + kc * 8;
            dst[q] = (sp ? OFF_AL : OFF_AH) + row * ROWB + kc * 16;
        } else {
            int c2 = c - 1024; int sp = c2 >> 10; int idx = c2 & 1023;
            int row = idx >> 2, kc = idx & 3;
            src[q] = (sp ? Bl : Bh) + (int64_t)row * ldb + kc * 8;
            dst[q] = (sp ? OFF_BL : OFF_BH) + row * ROWB + kc * 16;
        }
    }
    auto issue = [&](int s) {
        uint32_t stg = sbase + s * STAGE_B;
#pragma unroll
        for (int q = 0; q < 12; q++) {
            cp_async16(stg + dst[q], src[q]);
            src[q] += GBK;
        }
    };

    issue(0); cp_commit();
    issue(1); cp_commit();

    for (int it = 0; it < kiters; it++) {
        cp_wait1();
        __syncthreads();
        const char* stg = sm + (it % PIPE) * STAGE_B;

#pragma unroll
        for (int ks = 0; ks < 2; ks++) {
            const int kb = ks * 32 + t * 4;
            uint32_t ah[4][4], al[4][4], bh[8][2], bl[8][2];
#pragma unroll
            for (int i = 0; i < 4; i++) {
                int r0 = wm * 64 + i * 16 + g;
                const char* p = stg + OFF_AH + r0 * ROWB + kb;
                ah[i][0] = *(const uint32_t*)(p);
                ah[i][1] = *(const uint32_t*)(p + 8 * ROWB);
                ah[i][2] = *(const uint32_t*)(p + 16);
                ah[i][3] = *(const uint32_t*)(p + 8 * ROWB + 16);
            }
#pragma unroll
            for (int j = 0; j < 8; j++) {
                int n = wn * 64 + j * 8 + g;
                const char* p = stg + OFF_BH + n * ROWB + kb;
                bh[j][0] = *(const uint32_t*)(p);
                bh[j][1] = *(const uint32_t*)(p + 16);
            }
#pragma unroll
            for (int i = 0; i < 4; i++)
#pragma unroll
                for (int j = 0; j < 8; j++) mma_bf16(acc[i][j], ah[i], bh[j]);

#pragma unroll
            for (int j = 0; j < 8; j++) {
                int n = wn * 64 + j * 8 + g;
                const char* p = stg + OFF_BL + n * ROWB + kb;
                bl[j][0] = *(const uint32_t*)(p);
                bl[j][1] = *(const uint32_t*)(p + 16);
            }
#pragma unroll
            for (int i = 0; i < 4; i++)
#pragma unroll
                for (int j = 0; j < 8; j++) mma_bf16(acc[i][j], ah[i], bl[j]);

#pragma unroll
            for (int i = 0; i < 4; i++) {
                int r0 = wm * 64 + i * 16 + g;
                const char* p = stg + OFF_AL + r0 * ROWB + kb;
                al[i][0] = *(const uint32_t*)(p);
                al[i][1] = *(const uint32_t*)(p + 8 * ROWB);
                al[i][2] = *(const uint32_t*)(p + 16);
                al[i][3] = *(const uint32_t*)(p + 8 * ROWB + 16);
            }
#pragma unroll
            for (int i = 0; i < 4; i++)
#pragma unroll
                for (int j = 0; j < 8; j++) mma_bf16(acc[i][j], al[i], bh[j]);
        }

        if (it + 2 < kiters) issue((it + 2) % PIPE);
        cp_commit();
    }
}

// ---------------- fused QKV projection GEMM + RoPE epilogue ------------------
// z=0: Q -> RoPE -> bf16 splits; z=1: K -> RoPE -> fp32; z=2: V -> fp32.
__global__ __launch_bounds__(256, 1)
void qkv_mma(const __nv_bfloat16* __restrict__ Xh, const __nv_bfloat16* __restrict__ Xl,
             const __nv_bfloat16* __restrict__ Wqh, const __nv_bfloat16* __restrict__ Wql,
             const __nv_bfloat16* __restrict__ Wkh, const __nv_bfloat16* __restrict__ Wkl,
             const __nv_bfloat16* __restrict__ Wvh, const __nv_bfloat16* __restrict__ Wvl,
             const int* __restrict__ pos_ids,
             __nv_bfloat16* __restrict__ Qh, __nv_bfloat16* __restrict__ Ql,
             float* __restrict__ K, float* __restrict__ V) {
    extern __shared__ __align__(16) char sm[];
    const int z = blockIdx.z;
    const int m0 = blockIdx.y * GBM, n0 = blockIdx.x * GBN;
    const __nv_bfloat16* Bh = (z == 0) ? Wqh : (z == 1) ? Wkh : Wvh;
    const __nv_bfloat16* Bl = (z == 0) ? Wql : (z == 1) ? Wkl : Wvl;
    float acc[4][8][4];
    gemm_split_core(Xh + (size_t)m0 * DMODEL, Xl + (size_t)m0 * DMODEL,
                    Bh + (size_t)n0 * DMODEL, Bl + (size_t)n0 * DMODEL,
                    DMODEL, DMODEL, DMODEL / GBK, sm, acc);

    const int lane = threadIdx.x & 31, wid = threadIdx.x >> 5;
    const int g = lane >> 2, t = lane & 3;
    const int wm = wid >> 2, wn = wid & 3;
    const bool do_rope = (z < 2) && (wn == 0);   // head-local cols 0..62

#pragma unroll
    for (int i = 0; i < 4; i++) {
        int m = m0 + wm * 64 + i * 16 + g;       // global token index
        float p0 = 0.f, p1 = 0.f;
        if (do_rope) {
            p0 = (float)pos_ids[m];
            p1 = (float)pos_ids[m + 8];
        }
#pragma unroll
        for (int j = 0; j < 8; j++) {
            int n = n0 + wn * 64 + j * 8 + t * 2;
            float v0 = acc[i][j][0], v1 = acc[i][j][1];
            float v2 = acc[i][j][2], v3 = acc[i][j][3];
            if (do_rope) {
                int f = j * 4 + t;
                float ivf = powf(10000.0f, -(2.0f * (float)f) / 64.0f);
                float a0 = p0 * ivf, a1 = p1 * ivf;
                float c0 = cosf(a0), s0 = sinf(a0);
                float c1 = cosf(a1), s1 = sinf(a1);
                float nv0 = c0 * v0 - s0 * v1, nv1 = s0 * v0 + c0 * v1;
                float nv2 = c1 * v2 - s1 * v3, nv3 = s1 * v2 + c1 * v3;
                v0 = nv0; v1 = nv1; v2 = nv2; v3 = nv3;
            }
            if (z == 0) {
                __nv_bfloat162 lo0, lo1;
                __nv_bfloat162 hi0 = split_hi2(v0, v1, lo0);
                __nv_bfloat162 hi1 = split_hi2(v2, v3, lo1);
                *(__nv_bfloat162*)&Qh[(size_t)m * DMODEL + n]       = hi0;
                *(__nv_bfloat162*)&Ql[(size_t)m * DMODEL + n]       = lo0;
                *(__nv_bfloat162*)&Qh[(size_t)(m + 8) * DMODEL + n] = hi1;
                *(__nv_bfloat162*)&Ql[(size_t)(m + 8) * DMODEL + n] = lo1;
            } else {
                float* C = (z == 1) ? K : V;
                *(float2*)&C[(size_t)m * DMODEL + n]       = make_float2(v0, v1);
                *(float2*)&C[(size_t)(m + 8) * DMODEL + n] = make_float2(v2, v3);
            }
        }
    }
}

// ---------------- QK^T GEMM: causal mask + scale + attention mask -----------
__global__ __launch_bounds__(256, 1)
void qk_mma(const __nv_bfloat16* __restrict__ Qh, const __nv_bfloat16* __restrict__ Ql,
            const __nv_bfloat16* __restrict__ Kh, const __nv_bfloat16* __restrict__ Kl,
            const float* __restrict__ am, float* __restrict__ Sc) {
    extern __shared__ __align__(16) char sm[];
    const int bh = blockIdx.z;
    const int b = bh >> 4, h = bh & 15;
    const int m0 = blockIdx.y * GBM, n0 = blockIdx.x * GBN;
    if (n0 > m0 + (GBM - 1)) return;   // fully masked: softmax never reads it

    float* Cb = Sc + (size_t)bh * S_LEN * S_LEN;
    const size_t aoff = (size_t)b * S_LEN * DMODEL + (size_t)h * HDIM + (size_t)m0 * DMODEL;
    const size_t boff = (size_t)bh * S_LEN * HDIM + (size_t)n0 * HDIM;
    float acc[4][8][4];
    gemm_split_core(Qh + aoff, Ql + aoff, Kh + boff, Kl + boff,
                    DMODEL, HDIM, HDIM / GBK, sm, acc);

    const int lane = threadIdx.x & 31, wid = threadIdx.x >> 5;
    const int g = lane >> 2, t = lane & 3;
    const int wm = wid >> 2, wn = wid & 3;
    const float scale = 1.0f / 16.0f;
#pragma unroll
    for (int i = 0; i < 4; i++) {
        int m = m0 + wm * 64 + i * 16 + g;
#pragma unroll
        for (int j = 0; j < 8; j++) {
            int n = n0 + wn * 64 + j * 8 + t * 2;
            float amv0 = am[b * S_LEN + n], amv1 = am[b * S_LEN + n + 1];
            float v0 = (n     <= m) ? (acc[i][j][0] * scale + amv0) : -1e30f;
            float v1 = (n + 1 <= m) ? (acc[i][j][1] * scale + amv1) : -1e30f;
            float v2 = (n     <= m + 8) ? (acc[i][j][2] * scale + amv0) : -1e30f;
            float v3 = (n + 1 <= m + 8) ? (acc[i][j][3] * scale + amv1) : -1e30f;
            *(float2*)&Cb[(size_t)m * S_LEN + n]       = make_float2(v0, v1);
            *(float2*)&Cb[(size_t)(m + 8) * S_LEN + n] = make_float2(v2, v3);
        }
    }
}

// ---------------- PV GEMM -> bf16 split O epilogue ---------------------------
__global__ __launch_bounds__(256, 1)
void pv_mma(const __nv_bfloat16* __restrict__ Ph, const __nv_bfloat16* __restrict__ Pl,
            const __nv_bfloat16* __restrict__ Vth, const __nv_bfloat16* __restrict__ Vtl,
            __nv_bfloat16* __restrict__ Oh, __nv_bfloat16* __restrict__ Ol) {
    extern __shared__ __align__(16) char sm[];
    const int bh = blockIdx.z;
    const int b = bh >> 4, h = bh & 15;
    const int m0 = blockIdx.y * GBM;
    const size_t aoff = (size_t)bh * S_LEN * S_LEN + (size_t)m0 * S_LEN;
    const size_t boff = (size_t)bh * HDIM * S_LEN;
    float acc[4][8][4];
    gemm_split_core(Ph + aoff, Pl + aoff, Vth + boff, Vtl + boff,
                    S_LEN, S_LEN, (m0 + GBM) / GBK, sm, acc);

    const int lane = threadIdx.x & 31, wid = threadIdx.x >> 5;
    const int g = lane >> 2, t = lane & 3;
    const int wm = wid >> 2, wn = wid & 3;
#pragma unroll
    for (int i = 0; i < 4; i++) {
        int m = m0 + wm * 64 + i * 16 + g;
        size_t tok0 = (size_t)b * S_LEN + m;
#pragma unroll
        for (int j = 0; j < 8; j++) {
            int n = wn * 64 + j * 8 + t * 2;
            __nv_bfloat162 lo0, lo1;
            __nv_bfloat162 hi0 = split_hi2(acc[i][j][0], acc[i][j][1], lo0);
            __nv_bfloat162 hi1 = split_hi2(acc[i][j][2], acc[i][j][3], lo1);
            *(__nv_bfloat162*)&Oh[tok0 * DMODEL + h * HDIM + n]       = hi0;
            *(__nv_bfloat162*)&Ol[tok0 * DMODEL + h * HDIM + n]       = lo0;
            *(__nv_bfloat162*)&Oh[(tok0 + 8) * DMODEL + h * HDIM + n] = hi1;
            *(__nv_bfloat162*)&Ol[(tok0 + 8) * DMODEL + h * HDIM + n] = lo1;
        }
    }
}

// ---------------- output projection GEMM -------------------------------------
__global__ __launch_bounds__(256, 1)
void gemm_proj(const __nv_bfloat16* __restrict__ Agh, const __nv_bfloat16* __restrict__ Agl,
               const __nv_bfloat16* __restrict__ Bgh, const __nv_bfloat16* __restrict__ Bgl,
               float* __restrict__ C) {
    extern __shared__ __align__(16) char sm[];
    const int m0 = blockIdx.y * GBM, n0 = blockIdx.x * GBN;
    float acc[4][8][4];
    gemm_split_core(Agh + (size_t)m0 * DMODEL, Agl + (size_t)m0 * DMODEL,
                    Bgh + (size_t)n0 * DMODEL, Bgl + (size_t)n0 * DMODEL,
                    DMODEL, DMODEL, DMODEL / GBK, sm, acc);
    const int lane = threadIdx.x & 31, wid = threadIdx.x >> 5;
    const int g = lane >> 2, t = lane & 3;
    const int wm = wid >> 2, wn = wid & 3;
#pragma unroll
    for (int i = 0; i < 4; i++) {
        int m = m0 + wm * 64 + i * 16 + g;
#pragma unroll
        for (int j = 0; j < 8; j++) {
            int n = n0 + wn * 64 + j * 8 + t * 2;
            *(float2*)&C[(size_t)m * DMODEL + n]       = make_float2(acc[i][j][0], acc[i][j][1]);
            *(float2*)&C[(size_t)(m + 8) * DMODEL + n] = make_float2(acc[i][j][2], acc[i][j][3]);
        }
    }
}

// ---------------- fp32 -> (bf16 hi, bf16 lo) split conversion ----------------
__global__ __launch_bounds__(256)
void conv_split_kernel(const float4* __restrict__ x,
                       __nv_bfloat162* __restrict__ hi,
                       __nv_bfloat162* __restrict__ lo) {
    int i = blockIdx.x * 256 + threadIdx.x;
    float4 v = x[i];
    __nv_bfloat162 lo0, lo1;
    __nv_bfloat162 hi0 = split_hi2(v.x, v.y, lo0);
    __nv_bfloat162 hi1 = split_hi2(v.z, v.w, lo1);
    hi[2 * i] = hi0; hi[2 * i + 1] = hi1;
    lo[2 * i] = lo0; lo[2 * i + 1] = lo1;
}

// ---------------- inverse cache maps -----------------------------------------
__global__ __launch_bounds__(256)
void init_inv(int* __restrict__ inv_k, int* __restrict__ inv_v) {
    int i = blockIdx.x * 256 + threadIdx.x;
    inv_k[i] = -1;
    inv_v[i] = -1;
}
__global__ __launch_bounds__(256)
void scatter_inv(const int* __restrict__ nkl, const int* __restrict__ nvl,
                 int* __restrict__ inv_k, int* __restrict__ inv_v) {
    int t = blockIdx.x * 256 + threadIdx.x;
    inv_k[nkl[t]] = t;
    inv_v[nvl[t]] = t;
}

// ---------------- fused K gather + split (reads K or layer_past) -------------
__global__ __launch_bounds__(256)
void kgather_split(const float4* __restrict__ Kf, const float4* __restrict__ lpk,
                   const int* __restrict__ vki, const int* __restrict__ inv_k,
                   __nv_bfloat162* __restrict__ Kgh,
                   __nv_bfloat162* __restrict__ Kgl) {
    int i = blockIdx.x * 256 + threadIdx.x;       // over NTOK*1024 float4s
    int d4 = i & 63;
    int t  = (i >> 6) & 2047;
    int h  = (i >> 17) & 15;
    int b  = i >> 21;
    int j = vki[b * S_LEN + t];
    int tok = inv_k[j];
    float4 v = (tok >= 0) ? Kf[(size_t)tok * 1024 + h * 64 + d4]
                          : lpk[(size_t)j * 1024 + h * 64 + d4];
    __nv_bfloat162 lo0, lo1;
    __nv_bfloat162 hi0 = split_hi2(v.x, v.y, lo0);
    __nv_bfloat162 hi1 = split_hi2(v.z, v.w, lo1);
    size_t o = (size_t)i * 2;
    Kgh[o] = hi0; Kgh[o + 1] = hi1;
    Kgl[o] = lo0; Kgl[o + 1] = lo1;
}

// ---------------- fused V gather + transpose + split -------------------------
__global__ __launch_bounds__(256)
void vgather_trans_split(const float* __restrict__ Vf, const float* __restrict__ lpv,
                         const int* __restrict__ vvi, const int* __restrict__ inv_v,
                         __nv_bfloat16* __restrict__ Vth,
                         __nv_bfloat16* __restrict__ Vtl) {
    __shared__ float tile[32][33];
    const int bh = blockIdx.z;
    const int b = bh >> 4, h = bh & 15;
    const int s0 = blockIdx.x * 32, d0 = blockIdx.y * 32;
    const int tx = threadIdx.x & 31, ty = threadIdx.x >> 5;
#pragma unroll
    for (int r = 0; r < 32; r += 8) {
        int j = vvi[b * S_LEN + s0 + ty + r];
        int tok = inv_v[j];
        const float* src = (tok >= 0) ? Vf + (size_t)tok * DMODEL
                                      : lpv + (size_t)j * DMODEL;
        tile[ty + r][tx] = src[h * HDIM + d0 + tx];
    }
    __syncthreads();
    __nv_bfloat16* dh = Vth + (size_t)bh * HDIM * S_LEN;
    __nv_bfloat16* dl = Vtl + (size_t)bh * HDIM * S_LEN;
#pragma unroll
    for (int r = 0; r < 32; r += 8) {
        float v = tile[tx][ty + r];
        __nv_bfloat16 hh = __float2bfloat16(v);
        __nv_bfloat16 ll = __float2bfloat16(v - __bfloat162float(hh));
        size_t o = (size_t)(d0 + ty + r) * S_LEN + s0 + tx;
        dh[o] = hh;
        dl[o] = ll;
    }
}

// ---------------- index dtype normalization ---------------------------------
__global__ __launch_bounds__(256)
void conv_idx_kernel(const unsigned int* __restrict__ raw,
                     int* __restrict__ out, int n) {
    bool is64 = (raw[1] == 0u) && (raw[3] == 0u) && (raw[5] == 0u);
    int i = blockIdx.x * 256 + threadIdx.x;
    if (i < n) out[i] = is64 ? (int)raw[2 * i] : (int)raw[i];
}

// ---------------- causal row softmax -> bf16 hi/lo prob splits ---------------
__global__ __launch_bounds__(256)
void softmax_split(const float* __restrict__ Sc,
                   __nv_bfloat16* __restrict__ Ph,
                   __nv_bfloat16* __restrict__ Pl) {
    __shared__ float sh[8];
    const int m = blockIdx.x & (S_LEN - 1);       // row within head
    const size_t base = (size_t)blockIdx.x * S_LEN;
    const int limit = ((m >> 7) + 1) << 7;        // pv reads k in [0, limit)
    const int tid = threadIdx.x;
    const int lane = tid & 31, wid = tid >> 5;
    float v[8];
    float mx = -INFINITY;
#pragma unroll
    for (int i = 0; i < 8; i++) {
        int n = tid + i * 256;
        v[i] = (n <= m) ? Sc[base + n] : -INFINITY;
        mx = fmaxf(mx, v[i]);
    }
#pragma unroll
    for (int o = 16; o; o >>= 1) mx = fmaxf(mx, __shfl_xor_sync(0xffffffffu, mx, o));
    if (lane == 0) sh[wid] = mx;
    __syncthreads();
    float mall = sh[0];
#pragma unroll
    for (int w = 1; w < 8; w++) mall = fmaxf(mall, sh[w]);
    __syncthreads();
    float s = 0.f;
#pragma unroll
    for (int i = 0; i < 8; i++) {
        v[i] = __expf(v[i] - mall);
        s += v[i];
    }
#pragma unroll
    for (int o = 16; o; o >>= 1) s += __shfl_xor_sync(0xffffffffu, s, o);
    if (lane == 0) sh[wid] = s;
    __syncthreads();
    float sall = 0.f;
#pragma unroll
    for (int w = 0; w < 8; w++) sall += sh[w];
    float inv = 1.0f / sall;
#pragma unroll
    for (int i = 0; i < 8; i++) {
        int n = tid + i * 256;
        if (n < limit) {
            float p = v[i] * inv;
            __nv_bfloat16 h = __float2bfloat16(p);
            Ph[base + n] = h;
            Pl[base + n] = __float2bfloat16(p - __bfloat162float(h));
        }
    }
}

// ---------------- host launcher ---------------------------------------------
extern "C" void kernel_launch(void* const* d_in, const int* in_sizes, int n_in,
                              void* d_out, int out_size) {
    (void)in_sizes; (void)n_in; (void)out_size;
    const float* hs  = (const float*)d_in[0];
    const float* Wq  = (const float*)d_in[1];
    const float* Wk  = (const float*)d_in[2];
    const float* Wv  = (const float*)d_in[3];
    const float* Wo  = (const float*)d_in[4];
    const float* lpk = (const float*)d_in[5];
    const float* lpv = (const float*)d_in[6];
    const float* am  = (const float*)d_in[7];
    const unsigned int* pos_raw = (const unsigned int*)d_in[8];
    const unsigned int* nkl_raw = (const unsigned int*)d_in[9];
    const unsigned int* nvl_raw = (const unsigned int*)d_in[10];
    const unsigned int* vki_raw = (const unsigned int*)d_in[11];
    const unsigned int* vvi_raw = (const unsigned int*)d_in[12];
    float* out = (float*)d_out;

    float *K, *V, *Sc;
    __nv_bfloat16 *Xh, *Xl, *Qh, *Ql, *Wqh, *Wql, *Wkh, *Wkl, *Wvh, *Wvl, *Woh, *Wol;
    __nv_bfloat16 *Kgh, *Kgl, *Vth, *Vtl, *Ph, *Pl;
    int *idx, *inv;
    cudaGetSymbolAddress((void**)&K,   g_K);
    cudaGetSymbolAddress((void**)&V,   g_V);
    cudaGetSymbolAddress((void**)&Sc,  g_Sc);
    cudaGetSymbolAddress((void**)&idx, g_idx);
    cudaGetSymbolAddress((void**)&inv, g_inv);
    cudaGetSymbolAddress((void**)&Xh,  g_Xh);
    cudaGetSymbolAddress((void**)&Xl,  g_Xl);
    cudaGetSymbolAddress((void**)&Qh,  g_Qh);
    cudaGetSymbolAddress((void**)&Ql,  g_Ql);
    cudaGetSymbolAddress((void**)&Wqh, g_Wqh);
    cudaGetSymbolAddress((void**)&Wql, g_Wql);
    cudaGetSymbolAddress((void**)&Wkh, g_Wkh);
    cudaGetSymbolAddress((void**)&Wkl, g_Wkl);
    cudaGetSymbolAddress((void**)&Wvh, g_Wvh);
    cudaGetSymbolAddress((void**)&Wvl, g_Wvl);
    cudaGetSymbolAddress((void**)&Woh, g_Woh);
    cudaGetSymbolAddress((void**)&Wol, g_Wol);
    cudaGetSymbolAddress((void**)&Kgh, g_Kgh);
    cudaGetSymbolAddress((void**)&Kgl, g_Kgl);
    cudaGetSymbolAddress((void**)&Vth, g_Vth);
    cudaGetSymbolAddress((void**)&Vtl, g_Vtl);
    cudaGetSymbolAddress((void**)&Ph,  g_Ph);
    cudaGetSymbolAddress((void**)&Pl,  g_Pl);
    int* pos = idx + 0 * NTOK;
    int* nkl = idx + 1 * NTOK;
    int* nvl = idx + 2 * NTOK;
    int* vki = idx + 3 * NTOK;
    int* vvi = idx + 4 * NTOK;
    int* inv_k = inv + 0 * NTOK;
    int* inv_v = inv + 1 * NTOK;

    cudaFuncSetAttribute(qkv_mma,   cudaFuncAttributeMaxDynamicSharedMemorySize, GEMM_SMEM);
    cudaFuncSetAttribute(gemm_proj, cudaFuncAttributeMaxDynamicSharedMemorySize, GEMM_SMEM);
    cudaFuncSetAttribute(qk_mma,    cudaFuncAttributeMaxDynamicSharedMemorySize, GEMM_SMEM);
    cudaFuncSetAttribute(pv_mma,    cudaFuncAttributeMaxDynamicSharedMemorySize, GEMM_SMEM);

    conv_idx_kernel<<<16, 256>>>(pos_raw, pos, NTOK);
    conv_idx_kernel<<<16, 256>>>(nkl_raw, nkl, NTOK);
    conv_idx_kernel<<<16, 256>>>(nvl_raw, nvl, NTOK);
    conv_idx_kernel<<<16, 256>>>(vki_raw, vki, NTOK);
    conv_idx_kernel<<<16, 256>>>(vvi_raw, vvi, NTOK);
    init_inv<<<16, 256>>>(inv_k, inv_v);
    scatter_inv<<<16, 256>>>(nkl, nvl, inv_k, inv_v);

    const int CONV_BLOCKS = (NTOK * DMODEL / 4) / 256;  // 16384

    // ---- all splits up front (no serialization with GEMMs) ----
    conv_split_kernel<<<CONV_BLOCKS, 256>>>((const float4*)hs,
                                            (__nv_bfloat162*)Xh, (__nv_bfloat162*)Xl);
    conv_split_kernel<<<CONV_BLOCKS, 256>>>((const float4*)Wq,
                                            (__nv_bfloat162*)Wqh, (__nv_bfloat162*)Wql);
    conv_split_kernel<<<CONV_BLOCKS, 256>>>((const float4*)Wk,
                                            (__nv_bfloat162*)Wkh, (__nv_bfloat162*)Wkl);
    conv_split_kernel<<<CONV_BLOCKS, 256>>>((const float4*)Wv,
                                            (__nv_bfloat162*)Wvh, (__nv_bfloat162*)Wvl);
    conv_split_kernel<<<CONV_BLOCKS, 256>>>((const float4*)Wo,
                                            (__nv_bfloat162*)Woh, (__nv_bfloat162*)Wol);

    // ---- fused QKV projection + RoPE (one launch, 1536 CTAs) ----
    qkv_mma<<<dim3(DMODEL / GBN, DMODEL / GBM, 3), 256, GEMM_SMEM>>>(
        Xh, Xl, Wqh, Wql, Wkh, Wkl, Wvh, Wvl, pos, Qh, Ql, K, V);

    // ---- cache-semantic gathers (inverse-index, no copy/scatter passes) ----
    kgather_split<<<16384, 256>>>((const float4*)K, (const float4*)lpk, vki, inv_k,
                                  (__nv_bfloat162*)Kgh, (__nv_bfloat162*)Kgl);
    vgather_trans_split<<<dim3(S_LEN / 32, HDIM / 32, BH), 256>>>(
        V, lpv, vvi, inv_v, Vth, Vtl);

    // ---- attention ----
    qk_mma<<<dim3(S_LEN / GBN, S_LEN / GBM, BH), 256, GEMM_SMEM>>>(
        Qh, Ql, Kgh, Kgl, am, Sc);
    softmax_split<<<BH * S_LEN, 256>>>(Sc, Ph, Pl);
    pv_mma<<<dim3(1, S_LEN / GBM, BH), 256, GEMM_SMEM>>>(Ph, Pl, Vth, Vtl, Xh, Xl);

    // ---- output projection ----
    gemm_proj<<<dim3(DMODEL / GBN, DMODEL / GBM), 256, GEMM_SMEM>>>(
        Xh, Xl, Woh, Wol, out);
}

// round 14
// speedup vs baseline: 2.6124x; 1.0528x over previous
#include <cuda_runtime.h>
#include <cuda_bf16.h>
#include <math.h>
#include <stdint.h>

// Problem constants (fixed by the dataset)
#define S_LEN 2048
#define NHEAD 16
#define HDIM  256
#define BATCH 2
#define DMODEL 4096
#define NTOK  4096              // BATCH * S_LEN
#define BH    32                // BATCH * NHEAD

// ---------------- scratch (device globals; no allocations allowed) ----------
__device__ float g_K [(size_t)NTOK * DMODEL];   // post-RoPE K (fp32, cache source)
__device__ float g_V [(size_t)NTOK * DMODEL];
__device__ float g_Sc[(size_t)BH * S_LEN * S_LEN]; // fp32 scores
__device__ int   g_idx[5][NTOK];
__device__ int   g_inv[2][NTOK];                // inverse cache maps (k, v)
// bf16 split buffers
__device__ __nv_bfloat16 g_Xh[(size_t)NTOK * DMODEL];   // hs splits, later O splits
__device__ __nv_bfloat16 g_Xl[(size_t)NTOK * DMODEL];
__device__ __nv_bfloat16 g_Qh[(size_t)NTOK * DMODEL];   // post-RoPE Q splits
__device__ __nv_bfloat16 g_Ql[(size_t)NTOK * DMODEL];
__device__ __nv_bfloat16 g_Wqh[(size_t)DMODEL * DMODEL];
__device__ __nv_bfloat16 g_Wql[(size_t)DMODEL * DMODEL];
__device__ __nv_bfloat16 g_Wkh[(size_t)DMODEL * DMODEL];
__device__ __nv_bfloat16 g_Wkl[(size_t)DMODEL * DMODEL];
__device__ __nv_bfloat16 g_Wvh[(size_t)DMODEL * DMODEL];
__device__ __nv_bfloat16 g_Wvl[(size_t)DMODEL * DMODEL];
__device__ __nv_bfloat16 g_Woh[(size_t)DMODEL * DMODEL];
__device__ __nv_bfloat16 g_Wol[(size_t)DMODEL * DMODEL];
__device__ __nv_bfloat16 g_Kgh[(size_t)NTOK * DMODEL];  // gathered K split [BH][S][HD]
__device__ __nv_bfloat16 g_Kgl[(size_t)NTOK * DMODEL];
__device__ __nv_bfloat16 g_Vth[(size_t)NTOK * DMODEL];  // V^T split: [BH][HD][S]
__device__ __nv_bfloat16 g_Vtl[(size_t)NTOK * DMODEL];
__device__ __nv_bfloat16 g_Ph[(size_t)BH * S_LEN * S_LEN];  // prob split
__device__ __nv_bfloat16 g_Pl[(size_t)BH * S_LEN * S_LEN];

// ============================================================================
// helpers
// ============================================================================
__device__ __forceinline__ uint32_t smem_u32(const void* p) {
    uint32_t a;
    asm("{ .reg .u64 t; cvta.to.shared.u64 t, %1; cvt.u32.u64 %0, t; }"
        : "=r"(a) : "l"(p));
    return a;
}
__device__ __forceinline__ void cp_async16(uint32_t dst, const void* src) {
    asm volatile("cp.async.cg.shared.global [%0], [%1], 16;"
                 :: "r"(dst), "l"(src) : "memory");
}
__device__ __forceinline__ void cp_commit() {
    asm volatile("cp.async.commit_group;" ::: "memory");
}
__device__ __forceinline__ void cp_wait1() {
    asm volatile("cp.async.wait_group 1;" ::: "memory");
}
__device__ __forceinline__ void mma_bf16(float* d, const uint32_t* a, const uint32_t* b) {
    asm volatile(
        "mma.sync.aligned.m16n8k16.row.col.f32.bf16.bf16.f32 "
        "{%0,%1,%2,%3}, {%4,%5,%6,%7}, {%8,%9}, {%0,%1,%2,%3};"
        : "+f"(d[0]), "+f"(d[1]), "+f"(d[2]), "+f"(d[3])
        : "r"(a[0]), "r"(a[1]), "r"(a[2]), "r"(a[3]), "r"(b[0]), "r"(b[1]));
}
__device__ __forceinline__ __nv_bfloat162 split_hi2(float a, float b,
                                                    __nv_bfloat162& lo) {
    __nv_bfloat16 h0 = __float2bfloat16(a);
    __nv_bfloat16 h1 = __float2bfloat16(b);
    lo = __halves2bfloat162(__float2bfloat16(a - __bfloat162float(h0)),
                            __float2bfloat16(b - __bfloat162float(h1)));
    return __halves2bfloat162(h0, h1);
}

// ============================================================================
// shared bf16-split mma core: CTA tile 128(M) x 256(N) x 32(K), 8 warps (2x4),
// warp tile 64x64, 3-stage cp.async pipeline, 80B-padded smem rows.
// acc = Ah*Bh^T + Ah*Bl^T + Al*Bh^T over kiters*32 K elements.
// ============================================================================
#define GBM 128
#define GBN 256
#define GBK 32
#define ROWB 80
#define SM_A_SZ (GBM * ROWB)            // 10240
#define SM_B_SZ (GBN * ROWB)            // 20480
#define OFF_AH 0
#define OFF_AL SM_A_SZ
#define OFF_BH (2 * SM_A_SZ)
#define OFF_BL (2 * SM_A_SZ + SM_B_SZ)
#define STAGE_B (2 * SM_A_SZ + 2 * SM_B_SZ)  // 61440
#define PIPE 3
#define GEMM_SMEM (PIPE * STAGE_B)      // 184320

__device__ __forceinline__ void gemm_split_core(
    const __nv_bfloat16* __restrict__ Ah, const __nv_bfloat16* __restrict__ Al,
    const __nv_bfloat16* __restrict__ Bh, const __nv_bfloat16* __restrict__ Bl,
    int64_t lda, int64_t ldb, int kiters,
    char* sm, float acc[4][8][4])
{
    const uint32_t sbase = smem_u32(sm);
    const int tid  = threadIdx.x;
    const int lane = tid & 31;
    const int g = lane >> 2, t = lane & 3;
    const int wid = tid >> 5;
    const int wm = wid >> 2, wn = wid & 3;

#pragma unroll
    for (int i = 0; i < 4; i++)
#pragma unroll
        for (int j = 0; j < 8; j++)
#pragma unroll
            for (int r = 0; r < 4; r++) acc[i][j][r] = 0.f;

    const __nv_bfloat16* src[12];
    uint32_t dst[12];
#pragma unroll
    for (int q = 0; q < 12; q++) {
        int c = tid + q * 256;
        if (c < 1024) {
            int sp = c >> 9; int idx = c & 511;
            int row = idx >> 2, kc = idx & 3;
            src[q] = (sp ? Al : Ah) + (int64_t)row * lda + kc * 8;
            dst[q] = (sp ? OFF_AL : OFF_AH) + row * ROWB + kc * 16;
        } else {
            int c2 = c - 1024; int sp = c2 >> 10; int idx = c2 & 1023;
            int row = idx >> 2, kc = idx & 3;
            src[q] = (sp ? Bl : Bh) + (int64_t)row * ldb + kc * 8;
            dst[q] = (sp ? OFF_BL : OFF_BH) + row * ROWB + kc * 16;
        }
    }
    auto issue = [&](int s) {
        uint32_t stg = sbase + s * STAGE_B;
#pragma unroll
        for (int q = 0; q < 12; q++) {
            cp_async16(stg + dst[q], src[q]);
            src[q] += GBK;
        }
    };

    issue(0); cp_commit();
    issue(1); cp_commit();

    for (int it = 0; it < kiters; it++) {
        cp_wait1();
        __syncthreads();
        const char* stg = sm + (it % PIPE) * STAGE_B;

#pragma unroll
        for (int ks = 0; ks < 2; ks++) {
            const int kb = ks * 32 + t * 4;
            uint32_t ah[4][4], al[4][4], bh[8][2], bl[8][2];
#pragma unroll
            for (int i = 0; i < 4; i++) {
                int r0 = wm * 64 + i * 16 + g;
                const char* p = stg + OFF_AH + r0 * ROWB + kb;
                ah[i][0] = *(const uint32_t*)(p);
                ah[i][1] = *(const uint32_t*)(p + 8 * ROWB);
                ah[i][2] = *(const uint32_t*)(p + 16);
                ah[i][3] = *(const uint32_t*)(p + 8 * ROWB + 16);
            }
#pragma unroll
            for (int j = 0; j < 8; j++) {
                int n = wn * 64 + j * 8 + g;
                const char* p = stg + OFF_BH + n * ROWB + kb;
                bh[j][0] = *(const uint32_t*)(p);
                bh[j][1] = *(const uint32_t*)(p + 16);
            }
#pragma unroll
            for (int i = 0; i < 4; i++)
#pragma unroll
                for (int j = 0; j < 8; j++) mma_bf16(acc[i][j], ah[i], bh[j]);

#pragma unroll
            for (int j = 0; j < 8; j++) {
                int n = wn * 64 + j * 8 + g;
                const char* p = stg + OFF_BL + n * ROWB + kb;
                bl[j][0] = *(const uint32_t*)(p);
                bl[j][1] = *(const uint32_t*)(p + 16);
            }
#pragma unroll
            for (int i = 0; i < 4; i++)
#pragma unroll
                for (int j = 0; j < 8; j++) mma_bf16(acc[i][j], ah[i], bl[j]);

#pragma unroll
            for (int i = 0; i < 4; i++) {
                int r0 = wm * 64 + i * 16 + g;
                const char* p = stg + OFF_AL + r0 * ROWB + kb;
                al[i][0] = *(const uint32_t*)(p);
                al[i][1] = *(const uint32_t*)(p + 8 * ROWB);
                al[i][2] = *(const uint32_t*)(p + 16);
                al[i][3] = *(const uint32_t*)(p + 8 * ROWB + 16);
            }
#pragma unroll
            for (int i = 0; i < 4; i++)
#pragma unroll
                for (int j = 0; j < 8; j++) mma_bf16(acc[i][j], al[i], bh[j]);
        }

        if (it + 2 < kiters) issue((it + 2) % PIPE);
        cp_commit();
    }
}

// ---------------- fused QKV projection GEMM + RoPE epilogue ------------------
// z=0: Q -> RoPE -> bf16 splits; z=1: K -> RoPE -> fp32; z=2: V -> fp32.
__global__ __launch_bounds__(256, 1)
void qkv_mma(const __nv_bfloat16* __restrict__ Xh, const __nv_bfloat16* __restrict__ Xl,
             const __nv_bfloat16* __restrict__ Wqh, const __nv_bfloat16* __restrict__ Wql,
             const __nv_bfloat16* __restrict__ Wkh, const __nv_bfloat16* __restrict__ Wkl,
             const __nv_bfloat16* __restrict__ Wvh, const __nv_bfloat16* __restrict__ Wvl,
             const int* __restrict__ pos_ids,
             __nv_bfloat16* __restrict__ Qh, __nv_bfloat16* __restrict__ Ql,
             float* __restrict__ K, float* __restrict__ V) {
    extern __shared__ __align__(16) char sm[];
    const int z = blockIdx.z;
    const int m0 = blockIdx.y * GBM, n0 = blockIdx.x * GBN;
    const __nv_bfloat16* Bh = (z == 0) ? Wqh : (z == 1) ? Wkh : Wvh;
    const __nv_bfloat16* Bl = (z == 0) ? Wql : (z == 1) ? Wkl : Wvl;
    float acc[4][8][4];
    gemm_split_core(Xh + (size_t)m0 * DMODEL, Xl + (size_t)m0 * DMODEL,
                    Bh + (size_t)n0 * DMODEL, Bl + (size_t)n0 * DMODEL,
                    DMODEL, DMODEL, DMODEL / GBK, sm, acc);

    const int lane = threadIdx.x & 31, wid = threadIdx.x >> 5;
    const int g = lane >> 2, t = lane & 3;
    const int wm = wid >> 2, wn = wid & 3;
    const bool do_rope = (z < 2) && (wn == 0);   // head-local cols 0..62

#pragma unroll
    for (int i = 0; i < 4; i++) {
        int m = m0 + wm * 64 + i * 16 + g;       // global token index
        float p0 = 0.f, p1 = 0.f;
        if (do_rope) {
            p0 = (float)pos_ids[m];
            p1 = (float)pos_ids[m + 8];
        }
#pragma unroll
        for (int j = 0; j < 8; j++) {
            int n = n0 + wn * 64 + j * 8 + t * 2;
            float v0 = acc[i][j][0], v1 = acc[i][j][1];
            float v2 = acc[i][j][2], v3 = acc[i][j][3];
            if (do_rope) {
                int f = j * 4 + t;
                // 10000^(-2f/64) = exp(-f * ln(10000)/32)
                float ivf = __expf(-0.28782313662425572f * (float)f);
                float s0, c0, s1, c1;
                __sincosf(p0 * ivf, &s0, &c0);
                __sincosf(p1 * ivf, &s1, &c1);
                float nv0 = c0 * v0 - s0 * v1, nv1 = s0 * v0 + c0 * v1;
                float nv2 = c1 * v2 - s1 * v3, nv3 = s1 * v2 + c1 * v3;
                v0 = nv0; v1 = nv1; v2 = nv2; v3 = nv3;
            }
            if (z == 0) {
                __nv_bfloat162 lo0, lo1;
                __nv_bfloat162 hi0 = split_hi2(v0, v1, lo0);
                __nv_bfloat162 hi1 = split_hi2(v2, v3, lo1);
                *(__nv_bfloat162*)&Qh[(size_t)m * DMODEL + n]       = hi0;
                *(__nv_bfloat162*)&Ql[(size_t)m * DMODEL + n]       = lo0;
                *(__nv_bfloat162*)&Qh[(size_t)(m + 8) * DMODEL + n] = hi1;
                *(__nv_bfloat162*)&Ql[(size_t)(m + 8) * DMODEL + n] = lo1;
            } else {
                float* C = (z == 1) ? K : V;
                *(float2*)&C[(size_t)m * DMODEL + n]       = make_float2(v0, v1);
                *(float2*)&C[(size_t)(m + 8) * DMODEL + n] = make_float2(v2, v3);
            }
        }
    }
}

// ---------------- QK^T GEMM: causal mask + scale + attention mask -----------
__global__ __launch_bounds__(256, 1)
void qk_mma(const __nv_bfloat16* __restrict__ Qh, const __nv_bfloat16* __restrict__ Ql,
            const __nv_bfloat16* __restrict__ Kh, const __nv_bfloat16* __restrict__ Kl,
            const float* __restrict__ am, float* __restrict__ Sc) {
    extern __shared__ __align__(16) char sm[];
    const int bh = blockIdx.z;
    const int b = bh >> 4, h = bh & 15;
    const int m0 = blockIdx.y * GBM, n0 = blockIdx.x * GBN;
    if (n0 > m0 + (GBM - 1)) return;   // fully masked: softmax never reads it

    float* Cb = Sc + (size_t)bh * S_LEN * S_LEN;
    const size_t aoff = (size_t)b * S_LEN * DMODEL + (size_t)h * HDIM + (size_t)m0 * DMODEL;
    const size_t boff = (size_t)bh * S_LEN * HDIM + (size_t)n0 * HDIM;
    float acc[4][8][4];
    gemm_split_core(Qh + aoff, Ql + aoff, Kh + boff, Kl + boff,
                    DMODEL, HDIM, HDIM / GBK, sm, acc);

    const int lane = threadIdx.x & 31, wid = threadIdx.x >> 5;
    const int g = lane >> 2, t = lane & 3;
    const int wm = wid >> 2, wn = wid & 3;
    const float scale = 1.0f / 16.0f;
#pragma unroll
    for (int i = 0; i < 4; i++) {
        int m = m0 + wm * 64 + i * 16 + g;
#pragma unroll
        for (int j = 0; j < 8; j++) {
            int n = n0 + wn * 64 + j * 8 + t * 2;
            float amv0 = am[b * S_LEN + n], amv1 = am[b * S_LEN + n + 1];
            float v0 = (n     <= m) ? (acc[i][j][0] * scale + amv0) : -1e30f;
            float v1 = (n + 1 <= m) ? (acc[i][j][1] * scale + amv1) : -1e30f;
            float v2 = (n     <= m + 8) ? (acc[i][j][2] * scale + amv0) : -1e30f;
            float v3 = (n + 1 <= m + 8) ? (acc[i][j][3] * scale + amv1) : -1e30f;
            *(float2*)&Cb[(size_t)m * S_LEN + n]       = make_float2(v0, v1);
            *(float2*)&Cb[(size_t)(m + 8) * S_LEN + n] = make_float2(v2, v3);
        }
    }
}

// ---------------- PV GEMM -> bf16 split O epilogue ---------------------------
__global__ __launch_bounds__(256, 1)
void pv_mma(const __nv_bfloat16* __restrict__ Ph, const __nv_bfloat16* __restrict__ Pl,
            const __nv_bfloat16* __restrict__ Vth, const __nv_bfloat16* __restrict__ Vtl,
            __nv_bfloat16* __restrict__ Oh, __nv_bfloat16* __restrict__ Ol) {
    extern __shared__ __align__(16) char sm[];
    const int bh = blockIdx.z;
    const int b = bh >> 4, h = bh & 15;
    const int m0 = blockIdx.y * GBM;
    const size_t aoff = (size_t)bh * S_LEN * S_LEN + (size_t)m0 * S_LEN;
    const size_t boff = (size_t)bh * HDIM * S_LEN;
    float acc[4][8][4];
    gemm_split_core(Ph + aoff, Pl + aoff, Vth + boff, Vtl + boff,
                    S_LEN, S_LEN, (m0 + GBM) / GBK, sm, acc);

    const int lane = threadIdx.x & 31, wid = threadIdx.x >> 5;
    const int g = lane >> 2, t = lane & 3;
    const int wm = wid >> 2, wn = wid & 3;
#pragma unroll
    for (int i = 0; i < 4; i++) {
        int m = m0 + wm * 64 + i * 16 + g;
        size_t tok0 = (size_t)b * S_LEN + m;
#pragma unroll
        for (int j = 0; j < 8; j++) {
            int n = wn * 64 + j * 8 + t * 2;
            __nv_bfloat162 lo0, lo1;
            __nv_bfloat162 hi0 = split_hi2(acc[i][j][0], acc[i][j][1], lo0);
            __nv_bfloat162 hi1 = split_hi2(acc[i][j][2], acc[i][j][3], lo1);
            *(__nv_bfloat162*)&Oh[tok0 * DMODEL + h * HDIM + n]       = hi0;
            *(__nv_bfloat162*)&Ol[tok0 * DMODEL + h * HDIM + n]       = lo0;
            *(__nv_bfloat162*)&Oh[(tok0 + 8) * DMODEL + h * HDIM + n] = hi1;
            *(__nv_bfloat162*)&Ol[(tok0 + 8) * DMODEL + h * HDIM + n] = lo1;
        }
    }
}

// ---------------- output projection GEMM -------------------------------------
__global__ __launch_bounds__(256, 1)
void gemm_proj(const __nv_bfloat16* __restrict__ Agh, const __nv_bfloat16* __restrict__ Agl,
               const __nv_bfloat16* __restrict__ Bgh, const __nv_bfloat16* __restrict__ Bgl,
               float* __restrict__ C) {
    extern __shared__ __align__(16) char sm[];
    const int m0 = blockIdx.y * GBM, n0 = blockIdx.x * GBN;
    float acc[4][8][4];
    gemm_split_core(Agh + (size_t)m0 * DMODEL, Agl + (size_t)m0 * DMODEL,
                    Bgh + (size_t)n0 * DMODEL, Bgl + (size_t)n0 * DMODEL,
                    DMODEL, DMODEL, DMODEL / GBK, sm, acc);
    const int lane = threadIdx.x & 31, wid = threadIdx.x >> 5;
    const int g = lane >> 2, t = lane & 3;
    const int wm = wid >> 2, wn = wid & 3;
#pragma unroll
    for (int i = 0; i < 4; i++) {
        int m = m0 + wm * 64 + i * 16 + g;
#pragma unroll
        for (int j = 0; j < 8; j++) {
            int n = n0 + wn * 64 + j * 8 + t * 2;
            *(float2*)&C[(size_t)m * DMODEL + n]       = make_float2(acc[i][j][0], acc[i][j][1]);
            *(float2*)&C[(size_t)(m + 8) * DMODEL + n] = make_float2(acc[i][j][2], acc[i][j][3]);
        }
    }
}

// ---------------- fp32 -> (bf16 hi, bf16 lo) split conversion ----------------
__global__ __launch_bounds__(256)
void conv_split_kernel(const float4* __restrict__ x,
                       __nv_bfloat162* __restrict__ hi,
                       __nv_bfloat162* __restrict__ lo) {
    int i = blockIdx.x * 256 + threadIdx.x;
    float4 v = x[i];
    __nv_bfloat162 lo0, lo1;
    __nv_bfloat162 hi0 = split_hi2(v.x, v.y, lo0);
    __nv_bfloat162 hi1 = split_hi2(v.z, v.w, lo1);
    hi[2 * i] = hi0; hi[2 * i + 1] = hi1;
    lo[2 * i] = lo0; lo[2 * i + 1] = lo1;
}

// ---------------- inverse cache maps -----------------------------------------
__global__ __launch_bounds__(256)
void init_inv(int* __restrict__ inv_k, int* __restrict__ inv_v) {
    int i = blockIdx.x * 256 + threadIdx.x;
    inv_k[i] = -1;
    inv_v[i] = -1;
}
__global__ __launch_bounds__(256)
void scatter_inv(const int* __restrict__ nkl, const int* __restrict__ nvl,
                 int* __restrict__ inv_k, int* __restrict__ inv_v) {
    int t = blockIdx.x * 256 + threadIdx.x;
    inv_k[nkl[t]] = t;
    inv_v[nvl[t]] = t;
}

// ---------------- fused K gather + split (reads K or layer_past) -------------
__global__ __launch_bounds__(256)
void kgather_split(const float4* __restrict__ Kf, const float4* __restrict__ lpk,
                   const int* __restrict__ vki, const int* __restrict__ inv_k,
                   __nv_bfloat162* __restrict__ Kgh,
                   __nv_bfloat162* __restrict__ Kgl) {
    int i = blockIdx.x * 256 + threadIdx.x;       // over NTOK*1024 float4s
    int d4 = i & 63;
    int t  = (i >> 6) & 2047;
    int h  = (i >> 17) & 15;
    int b  = i >> 21;
    int j = vki[b * S_LEN + t];
    int tok = inv_k[j];
    float4 v = (tok >= 0) ? Kf[(size_t)tok * 1024 + h * 64 + d4]
                          : lpk[(size_t)j * 1024 + h * 64 + d4];
    __nv_bfloat162 lo0, lo1;
    __nv_bfloat162 hi0 = split_hi2(v.x, v.y, lo0);
    __nv_bfloat162 hi1 = split_hi2(v.z, v.w, lo1);
    size_t o = (size_t)i * 2;
    Kgh[o] = hi0; Kgh[o + 1] = hi1;
    Kgl[o] = lo0; Kgl[o + 1] = lo1;
}

// ---------------- fused V gather + transpose + split -------------------------
__global__ __launch_bounds__(256)
void vgather_trans_split(const float* __restrict__ Vf, const float* __restrict__ lpv,
                         const int* __restrict__ vvi, const int* __restrict__ inv_v,
                         __nv_bfloat16* __restrict__ Vth,
                         __nv_bfloat16* __restrict__ Vtl) {
    __shared__ float tile[32][33];
    const int bh = blockIdx.z;
    const int b = bh >> 4, h = bh & 15;
    const int s0 = blockIdx.x * 32, d0 = blockIdx.y * 32;
    const int tx = threadIdx.x & 31, ty = threadIdx.x >> 5;
#pragma unroll
    for (int r = 0; r < 32; r += 8) {
        int j = vvi[b * S_LEN + s0 + ty + r];
        int tok = inv_v[j];
        const float* src = (tok >= 0) ? Vf + (size_t)tok * DMODEL
                                      : lpv + (size_t)j * DMODEL;
        tile[ty + r][tx] = src[h * HDIM + d0 + tx];
    }
    __syncthreads();
    __nv_bfloat16* dh = Vth + (size_t)bh * HDIM * S_LEN;
    __nv_bfloat16* dl = Vtl + (size_t)bh * HDIM * S_LEN;
#pragma unroll
    for (int r = 0; r < 32; r += 8) {
        float v = tile[tx][ty + r];
        __nv_bfloat16 hh = __float2bfloat16(v);
        __nv_bfloat16 ll = __float2bfloat16(v - __bfloat162float(hh));
        size_t o = (size_t)(d0 + ty + r) * S_LEN + s0 + tx;
        dh[o] = hh;
        dl[o] = ll;
    }
}

// ---------------- index dtype normalization ---------------------------------
__global__ __launch_bounds__(256)
void conv_idx_kernel(const unsigned int* __restrict__ raw,
                     int* __restrict__ out, int n) {
    bool is64 = (raw[1] == 0u) && (raw[3] == 0u) && (raw[5] == 0u);
    int i = blockIdx.x * 256 + threadIdx.x;
    if (i < n) out[i] = is64 ? (int)raw[2 * i] : (int)raw[i];
}

// ---------------- causal row softmax -> bf16 hi/lo prob splits ---------------
__global__ __launch_bounds__(256)
void softmax_split(const float* __restrict__ Sc,
                   __nv_bfloat16* __restrict__ Ph,
                   __nv_bfloat16* __restrict__ Pl) {
    __shared__ float sh[8];
    const int m = blockIdx.x & (S_LEN - 1);       // row within head
    const size_t base = (size_t)blockIdx.x * S_LEN;
    const int iu = m >> 8;                        // highest i with any n<=m
    const int limit = ((m >> 7) + 1) << 7;        // pv reads k in [0, limit)
    const int tid = threadIdx.x;
    const int lane = tid & 31, wid = tid >> 5;
    float v[8];
    float mx = -INFINITY;
#pragma unroll
    for (int i = 0; i < 8; i++) {
        v[i] = -INFINITY;
        if (i <= iu) {
            int n = tid + i * 256;
            v[i] = (n <= m) ? Sc[base + n] : -INFINITY;
            mx = fmaxf(mx, v[i]);
        }
    }
#pragma unroll
    for (int o = 16; o; o >>= 1) mx = fmaxf(mx, __shfl_xor_sync(0xffffffffu, mx, o));
    if (lane == 0) sh[wid] = mx;
    __syncthreads();
    float mall = sh[0];
#pragma unroll
    for (int w = 1; w < 8; w++) mall = fmaxf(mall, sh[w]);
    __syncthreads();
    float s = 0.f;
#pragma unroll
    for (int i = 0; i < 8; i++) {
        if (i <= iu) {
            v[i] = __expf(v[i] - mall);
            s += v[i];
        }
    }
#pragma unroll
    for (int o = 16; o; o >>= 1) s += __shfl_xor_sync(0xffffffffu, s, o);
    if (lane == 0) sh[wid] = s;
    __syncthreads();
    float sall = 0.f;
#pragma unroll
    for (int w = 0; w < 8; w++) sall += sh[w];
    float inv = 1.0f / sall;
#pragma unroll
    for (int i = 0; i < 8; i++) {
        if (i <= iu) {
            int n = tid + i * 256;
            if (n < limit) {
                float p = v[i] * inv;
                __nv_bfloat16 h = __float2bfloat16(p);
                Ph[base + n] = h;
                Pl[base + n] = __float2bfloat16(p - __bfloat162float(h));
            }
        }
    }
}

// ---------------- host launcher ---------------------------------------------
extern "C" void kernel_launch(void* const* d_in, const int* in_sizes, int n_in,
                              void* d_out, int out_size) {
    (void)in_sizes; (void)n_in; (void)out_size;
    const float* hs  = (const float*)d_in[0];
    const float* Wq  = (const float*)d_in[1];
    const float* Wk  = (const float*)d_in[2];
    const float* Wv  = (const float*)d_in[3];
    const float* Wo  = (const float*)d_in[4];
    const float* lpk = (const float*)d_in[5];
    const float* lpv = (const float*)d_in[6];
    const float* am  = (const float*)d_in[7];
    const unsigned int* pos_raw = (const unsigned int*)d_in[8];
    const unsigned int* nkl_raw = (const unsigned int*)d_in[9];
    const unsigned int* nvl_raw = (const unsigned int*)d_in[10];
    const unsigned int* vki_raw = (const unsigned int*)d_in[11];
    const unsigned int* vvi_raw = (const unsigned int*)d_in[12];
    float* out = (float*)d_out;

    float *K, *V, *Sc;
    __nv_bfloat16 *Xh, *Xl, *Qh, *Ql, *Wqh, *Wql, *Wkh, *Wkl, *Wvh, *Wvl, *Woh, *Wol;
    __nv_bfloat16 *Kgh, *Kgl, *Vth, *Vtl, *Ph, *Pl;
    int *idx, *inv;
    cudaGetSymbolAddress((void**)&K,   g_K);
    cudaGetSymbolAddress((void**)&V,   g_V);
    cudaGetSymbolAddress((void**)&Sc,  g_Sc);
    cudaGetSymbolAddress((void**)&idx, g_idx);
    cudaGetSymbolAddress((void**)&inv, g_inv);
    cudaGetSymbolAddress((void**)&Xh,  g_Xh);
    cudaGetSymbolAddress((void**)&Xl,  g_Xl);
    cudaGetSymbolAddress((void**)&Qh,  g_Qh);
    cudaGetSymbolAddress((void**)&Ql,  g_Ql);
    cudaGetSymbolAddress((void**)&Wqh, g_Wqh);
    cudaGetSymbolAddress((void**)&Wql, g_Wql);
    cudaGetSymbolAddress((void**)&Wkh, g_Wkh);
    cudaGetSymbolAddress((void**)&Wkl, g_Wkl);
    cudaGetSymbolAddress((void**)&Wvh, g_Wvh);
    cudaGetSymbolAddress((void**)&Wvl, g_Wvl);
    cudaGetSymbolAddress((void**)&Woh, g_Woh);
    cudaGetSymbolAddress((void**)&Wol, g_Wol);
    cudaGetSymbolAddress((void**)&Kgh, g_Kgh);
    cudaGetSymbolAddress((void**)&Kgl, g_Kgl);
    cudaGetSymbolAddress((void**)&Vth, g_Vth);
    cudaGetSymbolAddress((void**)&Vtl, g_Vtl);
    cudaGetSymbolAddress((void**)&Ph,  g_Ph);
    cudaGetSymbolAddress((void**)&Pl,  g_Pl);
    int* pos = idx + 0 * NTOK;
    int* nkl = idx + 1 * NTOK;
    int* nvl = idx + 2 * NTOK;
    int* vki = idx + 3 * NTOK;
    int* vvi = idx + 4 * NTOK;
    int* inv_k = inv + 0 * NTOK;
    int* inv_v = inv + 1 * NTOK;

    cudaFuncSetAttribute(qkv_mma,   cudaFuncAttributeMaxDynamicSharedMemorySize, GEMM_SMEM);
    cudaFuncSetAttribute(gemm_proj, cudaFuncAttributeMaxDynamicSharedMemorySize, GEMM_SMEM);
    cudaFuncSetAttribute(qk_mma,    cudaFuncAttributeMaxDynamicSharedMemorySize, GEMM_SMEM);
    cudaFuncSetAttribute(pv_mma,    cudaFuncAttributeMaxDynamicSharedMemorySize, GEMM_SMEM);

    conv_idx_kernel<<<16, 256>>>(pos_raw, pos, NTOK);
    conv_idx_kernel<<<16, 256>>>(nkl_raw, nkl, NTOK);
    conv_idx_kernel<<<16, 256>>>(nvl_raw, nvl, NTOK);
    conv_idx_kernel<<<16, 256>>>(vki_raw, vki, NTOK);
    conv_idx_kernel<<<16, 256>>>(vvi_raw, vvi, NTOK);
    init_inv<<<16, 256>>>(inv_k, inv_v);
    scatter_inv<<<16, 256>>>(nkl, nvl, inv_k, inv_v);

    const int CONV_BLOCKS = (NTOK * DMODEL / 4) / 256;  // 16384

    // ---- all splits up front (no serialization with GEMMs) ----
    conv_split_kernel<<<CONV_BLOCKS, 256>>>((const float4*)hs,
                                            (__nv_bfloat162*)Xh, (__nv_bfloat162*)Xl);
    conv_split_kernel<<<CONV_BLOCKS, 256>>>((const float4*)Wq,
                                            (__nv_bfloat162*)Wqh, (__nv_bfloat162*)Wql);
    conv_split_kernel<<<CONV_BLOCKS, 256>>>((const float4*)Wk,
                                            (__nv_bfloat162*)Wkh, (__nv_bfloat162*)Wkl);
    conv_split_kernel<<<CONV_BLOCKS, 256>>>((const float4*)Wv,
                                            (__nv_bfloat162*)Wvh, (__nv_bfloat162*)Wvl);
    conv_split_kernel<<<CONV_BLOCKS, 256>>>((const float4*)Wo,
                                            (__nv_bfloat162*)Woh, (__nv_bfloat162*)Wol);

    // ---- fused QKV projection + RoPE (one launch, 1536 CTAs) ----
    qkv_mma<<<dim3(DMODEL / GBN, DMODEL / GBM, 3), 256, GEMM_SMEM>>>(
        Xh, Xl, Wqh, Wql, Wkh, Wkl, Wvh, Wvl, pos, Qh, Ql, K, V);

    // ---- cache-semantic gathers (inverse-index, no copy/scatter passes) ----
    kgather_split<<<16384, 256>>>((const float4*)K, (const float4*)lpk, vki, inv_k,
                                  (__nv_bfloat162*)Kgh, (__nv_bfloat162*)Kgl);
    vgather_trans_split<<<dim3(S_LEN / 32, HDIM / 32, BH), 256>>>(
        V, lpv, vvi, inv_v, Vth, Vtl);

    // ---- attention ----
    qk_mma<<<dim3(S_LEN / GBN, S_LEN / GBM, BH), 256, GEMM_SMEM>>>(
        Qh, Ql, Kgh, Kgl, am, Sc);
    softmax_split<<<BH * S_LEN, 256>>>(Sc, Ph, Pl);
    pv_mma<<<dim3(1, S_LEN / GBM, BH), 256, GEMM_SMEM>>>(Ph, Pl, Vth, Vtl, Xh, Xl);

    // ---- output projection ----
    gemm_proj<<<dim3(DMODEL / GBN, DMODEL / GBM), 256, GEMM_SMEM>>>(
        Xh, Xl, Woh, Wol, out);
}